// round 1
// baseline (speedup 1.0000x reference)
#include <cuda_runtime.h>
#include <cuda_bf16.h>
#include <math.h>

// Problem constants
#define Lc   6
#define Dc   1024
#define Hc   16
#define DHc  64
#define FFc  4096
#define Bc   8
#define Nc   512
#define Mrows (Bc*Nc)          // 4096
#define EPSc 1e-12f

// ------------------------------------------------------------------
// Scratch (device globals; allocation is forbidden in kernel_launch)
// ------------------------------------------------------------------
__device__ float g_x [Mrows*Dc];
__device__ float g_t [Mrows*Dc];
__device__ float g_q [Mrows*Dc];
__device__ float g_k [Mrows*Dc];
__device__ float g_v [Mrows*Dc];
__device__ float g_ao[Mrows*Dc];
__device__ float g_s [(size_t)Bc*Hc*Nc*Nc];   // 134 MB scores
__device__ float g_ff[(size_t)Mrows*FFc];     // 67 MB ffn hidden

// ------------------------------------------------------------------
// Simple float4 copy
// ------------------------------------------------------------------
__global__ void copy4_kernel(float4* __restrict__ dst, const float4* __restrict__ src, int n4) {
    int i = blockIdx.x * blockDim.x + threadIdx.x;
    if (i < n4) dst[i] = src[i];
}

// ------------------------------------------------------------------
// SGEMM: C[M,N] = A[M,K] @ W[K,N] + bias[N]  (optional ReLU)
// 64x64 block tile, BK=16, 256 threads, 4x4 micro-tile.
// Requires: M%64==0, N%64==0, K%16==0 (true for all call sites).
// ------------------------------------------------------------------
template<bool RELU>
__global__ void __launch_bounds__(256)
gemm_bias_kernel(const float* __restrict__ A, const float* __restrict__ W,
                 const float* __restrict__ bias, float* __restrict__ C,
                 int M, int N, int K)
{
    __shared__ float As[16][64];   // k-major
    __shared__ float Bs[16][64];

    const int tid = threadIdx.x;
    const int tx = tid & 15;
    const int ty = tid >> 4;
    const int m0 = blockIdx.y * 64;
    const int n0 = blockIdx.x * 64;

    // loader coords
    const int arow = tid >> 2;        // 0..63
    const int akq  = (tid & 3) * 4;   // 0,4,8,12
    const int bkk  = tid >> 4;        // 0..15
    const int bnq  = (tid & 15) * 4;  // 0..60

    float acc[4][4];
#pragma unroll
    for (int i = 0; i < 4; i++)
#pragma unroll
        for (int j = 0; j < 4; j++) acc[i][j] = 0.f;

    for (int k0 = 0; k0 < K; k0 += 16) {
        float4 a4 = *(const float4*)&A[(size_t)(m0 + arow) * K + k0 + akq];
        As[akq + 0][arow] = a4.x;
        As[akq + 1][arow] = a4.y;
        As[akq + 2][arow] = a4.z;
        As[akq + 3][arow] = a4.w;
        *(float4*)&Bs[bkk][bnq] = *(const float4*)&W[(size_t)(k0 + bkk) * N + n0 + bnq];
        __syncthreads();

#pragma unroll
        for (int kk = 0; kk < 16; kk++) {
            float4 ra = *(const float4*)&As[kk][ty * 4];
            float4 rb = *(const float4*)&Bs[kk][tx * 4];
            acc[0][0] += ra.x * rb.x; acc[0][1] += ra.x * rb.y; acc[0][2] += ra.x * rb.z; acc[0][3] += ra.x * rb.w;
            acc[1][0] += ra.y * rb.x; acc[1][1] += ra.y * rb.y; acc[1][2] += ra.y * rb.z; acc[1][3] += ra.y * rb.w;
            acc[2][0] += ra.z * rb.x; acc[2][1] += ra.z * rb.y; acc[2][2] += ra.z * rb.z; acc[2][3] += ra.z * rb.w;
            acc[3][0] += ra.w * rb.x; acc[3][1] += ra.w * rb.y; acc[3][2] += ra.w * rb.z; acc[3][3] += ra.w * rb.w;
        }
        __syncthreads();
    }

    const int col0 = n0 + tx * 4;
    float4 b4 = *(const float4*)&bias[col0];
#pragma unroll
    for (int i = 0; i < 4; i++) {
        int row = m0 + ty * 4 + i;
        float4 o;
        o.x = acc[i][0] + b4.x;
        o.y = acc[i][1] + b4.y;
        o.z = acc[i][2] + b4.z;
        o.w = acc[i][3] + b4.w;
        if (RELU) {
            o.x = fmaxf(o.x, 0.f); o.y = fmaxf(o.y, 0.f);
            o.z = fmaxf(o.z, 0.f); o.w = fmaxf(o.w, 0.f);
        }
        *(float4*)&C[(size_t)row * N + col0] = o;
    }
}

// ------------------------------------------------------------------
// Attention scores: S[b,h,q,k] = (Q[b,q,h,:] . K[b,k,h,:]) / 8, masked.
// grid: (Nk/64, Nq/64, B*H); block 256.
// ------------------------------------------------------------------
__global__ void __launch_bounds__(256)
attn_scores_kernel(const float* __restrict__ Q, const float* __restrict__ Kmat,
                   const int* __restrict__ mask, float* __restrict__ S, int useMask)
{
    const int bh = blockIdx.z;
    const int b = bh >> 4;       // / Hc
    const int h = bh & 15;       // % Hc
    const float* Qb = Q + (size_t)b * Nc * Dc + h * DHc;
    const float* Kb = Kmat + (size_t)b * Nc * Dc + h * DHc;
    float* Sb = S + (size_t)bh * Nc * Nc;

    const int q0 = blockIdx.y * 64;
    const int k0 = blockIdx.x * 64;
    const int tid = threadIdx.x;
    const int tx = tid & 15;
    const int ty = tid >> 4;

    __shared__ float Qs[64][65];
    __shared__ float Ks[64][65];

    // load 64x64 tiles (1024 float4 slots each)
    for (int i = tid; i < 1024; i += 256) {
        int row = i >> 4;
        int dq = (i & 15) * 4;
        float4 a = *(const float4*)&Qb[(size_t)(q0 + row) * Dc + dq];
        Qs[row][dq + 0] = a.x; Qs[row][dq + 1] = a.y; Qs[row][dq + 2] = a.z; Qs[row][dq + 3] = a.w;
        float4 c = *(const float4*)&Kb[(size_t)(k0 + row) * Dc + dq];
        Ks[row][dq + 0] = c.x; Ks[row][dq + 1] = c.y; Ks[row][dq + 2] = c.z; Ks[row][dq + 3] = c.w;
    }
    __syncthreads();

    float acc[4][4];
#pragma unroll
    for (int i = 0; i < 4; i++)
#pragma unroll
        for (int j = 0; j < 4; j++) acc[i][j] = 0.f;

#pragma unroll 4
    for (int d = 0; d < 64; d++) {
        float ra[4], rb[4];
#pragma unroll
        for (int i = 0; i < 4; i++) ra[i] = Qs[ty * 4 + i][d];
#pragma unroll
        for (int j = 0; j < 4; j++) rb[j] = Ks[tx * 4 + j][d];
#pragma unroll
        for (int i = 0; i < 4; i++)
#pragma unroll
            for (int j = 0; j < 4; j++) acc[i][j] += ra[i] * rb[j];
    }

#pragma unroll
    for (int i = 0; i < 4; i++) {
        int qq = q0 + ty * 4 + i;
#pragma unroll
        for (int j = 0; j < 4; j++) {
            int kk = k0 + tx * 4 + j;
            float val = acc[i][j] * 0.125f;   // 1/sqrt(64)
            if (useMask) {
                if (mask[((size_t)b * Nc + qq) * Nc + kk] == 0) val = -10000.f;
            }
            Sb[(size_t)qq * Nc + kk] = val;
        }
    }
}

// ------------------------------------------------------------------
// Row softmax over 512 elements. One block (256 threads) per row.
// ------------------------------------------------------------------
__global__ void __launch_bounds__(256)
softmax512_kernel(float* __restrict__ S)
{
    const size_t row = blockIdx.x;
    float* p = S + row * Nc;
    const int tid = threadIdx.x;

    float v0 = p[tid];
    float v1 = p[tid + 256];

    __shared__ float red[8];
    // max reduce
    float m = fmaxf(v0, v1);
    for (int o = 16; o > 0; o >>= 1) m = fmaxf(m, __shfl_down_sync(0xffffffffu, m, o));
    if ((tid & 31) == 0) red[tid >> 5] = m;
    __syncthreads();
    if (tid < 32) {
        m = (tid < 8) ? red[tid] : -INFINITY;
        for (int o = 4; o > 0; o >>= 1) m = fmaxf(m, __shfl_down_sync(0xffffffffu, m, o));
        if (tid == 0) red[0] = m;
    }
    __syncthreads();
    m = red[0];
    __syncthreads();

    float e0 = expf(v0 - m);
    float e1 = expf(v1 - m);
    float s = e0 + e1;
    for (int o = 16; o > 0; o >>= 1) s += __shfl_down_sync(0xffffffffu, s, o);
    if ((tid & 31) == 0) red[tid >> 5] = s;
    __syncthreads();
    if (tid < 32) {
        s = (tid < 8) ? red[tid] : 0.f;
        for (int o = 4; o > 0; o >>= 1) s += __shfl_down_sync(0xffffffffu, s, o);
        if (tid == 0) red[0] = s;
    }
    __syncthreads();
    s = red[0];

    float inv = 1.f / s;
    p[tid] = e0 * inv;
    p[tid + 256] = e1 * inv;
}

// ------------------------------------------------------------------
// O[b,q,h,:] = P[b,h,q,:] @ V[b,:,h,:]   (M=512 per bh, N=64, K=512)
// grid: (Nq/64, B*H); block 256; BK=32.
// ------------------------------------------------------------------
__global__ void __launch_bounds__(256)
attn_pv_kernel(const float* __restrict__ S, const float* __restrict__ V, float* __restrict__ O)
{
    const int bh = blockIdx.y;
    const int b = bh >> 4;
    const int h = bh & 15;
    const float* Sb = S + (size_t)bh * Nc * Nc;
    const float* Vb = V + (size_t)b * Nc * Dc + h * DHc;
    float* Ob = O + (size_t)b * Nc * Dc + h * DHc;

    const int q0 = blockIdx.x * 64;
    const int tid = threadIdx.x;
    const int tx = tid & 15;
    const int ty = tid >> 4;

    __shared__ float Ps[64][33];
    __shared__ float Vs[32][64];

    float acc[4][4];
#pragma unroll
    for (int i = 0; i < 4; i++)
#pragma unroll
        for (int j = 0; j < 4; j++) acc[i][j] = 0.f;

    for (int kc = 0; kc < Nc; kc += 32) {
        // P tile 64x32 = 512 float4
        for (int i = tid; i < 512; i += 256) {
            int row = i >> 3;
            int kq = (i & 7) * 4;
            float4 a = *(const float4*)&Sb[(size_t)(q0 + row) * Nc + kc + kq];
            Ps[row][kq + 0] = a.x; Ps[row][kq + 1] = a.y; Ps[row][kq + 2] = a.z; Ps[row][kq + 3] = a.w;
        }
        // V tile 32x64 = 512 float4
        for (int i = tid; i < 512; i += 256) {
            int row = i >> 4;
            int nq = (i & 15) * 4;
            *(float4*)&Vs[row][nq] = *(const float4*)&Vb[(size_t)(kc + row) * Dc + nq];
        }
        __syncthreads();

#pragma unroll
        for (int kk = 0; kk < 32; kk++) {
            float ra[4];
#pragma unroll
            for (int i = 0; i < 4; i++) ra[i] = Ps[ty * 4 + i][kk];
            float4 rb = *(const float4*)&Vs[kk][tx * 4];
            acc[0][0] += ra[0] * rb.x; acc[0][1] += ra[0] * rb.y; acc[0][2] += ra[0] * rb.z; acc[0][3] += ra[0] * rb.w;
            acc[1][0] += ra[1] * rb.x; acc[1][1] += ra[1] * rb.y; acc[1][2] += ra[1] * rb.z; acc[1][3] += ra[1] * rb.w;
            acc[2][0] += ra[2] * rb.x; acc[2][1] += ra[2] * rb.y; acc[2][2] += ra[2] * rb.z; acc[2][3] += ra[2] * rb.w;
            acc[3][0] += ra[3] * rb.x; acc[3][1] += ra[3] * rb.y; acc[3][2] += ra[3] * rb.z; acc[3][3] += ra[3] * rb.w;
        }
        __syncthreads();
    }

#pragma unroll
    for (int i = 0; i < 4; i++) {
        int row = q0 + ty * 4 + i;
        float4 o;
        o.x = acc[i][0]; o.y = acc[i][1]; o.z = acc[i][2]; o.w = acc[i][3];
        *(float4*)&Ob[(size_t)row * Dc + tx * 4] = o;
    }
}

// ------------------------------------------------------------------
// out[row,:] = LayerNorm(A[row,:] + X[row,:]) * gamma + beta
// one block (256 threads) per row of 1024.
// ------------------------------------------------------------------
__global__ void __launch_bounds__(256)
add_ln_kernel(const float* __restrict__ A, const float* __restrict__ X,
              const float* __restrict__ gamma, const float* __restrict__ beta,
              float* __restrict__ out)
{
    const size_t row = blockIdx.x;
    const int tid = threadIdx.x;
    float vals[4];
    float s = 0.f, ss = 0.f;
#pragma unroll
    for (int i = 0; i < 4; i++) {
        int c = tid + i * 256;
        float v = A[row * Dc + c] + X[row * Dc + c];
        vals[i] = v;
        s += v;
        ss += v * v;
    }
    __shared__ float sa[8], sb[8];
    int lane = tid & 31, w = tid >> 5;
    for (int o = 16; o > 0; o >>= 1) {
        s  += __shfl_down_sync(0xffffffffu, s, o);
        ss += __shfl_down_sync(0xffffffffu, ss, o);
    }
    if (lane == 0) { sa[w] = s; sb[w] = ss; }
    __syncthreads();
    if (w == 0) {
        s  = (lane < 8) ? sa[lane] : 0.f;
        ss = (lane < 8) ? sb[lane] : 0.f;
        for (int o = 4; o > 0; o >>= 1) {
            s  += __shfl_down_sync(0xffffffffu, s, o);
            ss += __shfl_down_sync(0xffffffffu, ss, o);
        }
        if (lane == 0) { sa[0] = s; sb[0] = ss; }
    }
    __syncthreads();
    float mean = sa[0] * (1.f / Dc);
    float var = sb[0] * (1.f / Dc) - mean * mean;
    float inv = rsqrtf(var + EPSc);
#pragma unroll
    for (int i = 0; i < 4; i++) {
        int c = tid + i * 256;
        out[row * Dc + c] = gamma[c] * (vals[i] - mean) * inv + beta[c];
    }
}

// ------------------------------------------------------------------
// Host orchestration
// ------------------------------------------------------------------
extern "C" void kernel_launch(void* const* d_in, const int* in_sizes, int n_in,
                              void* d_out, int out_size)
{
    const float* trg  = (const float*)d_in[0];   // [8,512,1024]
    const float* enc  = (const float*)d_in[1];   // [8,512,1024]
    const int*   mask = (const int*)  d_in[2];   // [8,512,512]
    const float* sa_w = (const float*)d_in[3];   // [6,4,1024,1024]
    const float* sa_b = (const float*)d_in[4];   // [6,4,1024]
    const float* ca_w = (const float*)d_in[5];
    const float* ca_b = (const float*)d_in[6];
    const float* ln_g = (const float*)d_in[7];   // [6,3,1024]
    const float* ln_b = (const float*)d_in[8];
    const float* w1   = (const float*)d_in[9];   // [6,1024,4096]
    const float* b1   = (const float*)d_in[10];  // [6,4096]
    const float* w2   = (const float*)d_in[11];  // [6,4096,1024]
    const float* b2   = (const float*)d_in[12];  // [6,1024]
    float* out = (float*)d_out;

    float *x, *t, *q, *k, *v, *ao, *s, *ff;
    cudaGetSymbolAddress((void**)&x,  g_x);
    cudaGetSymbolAddress((void**)&t,  g_t);
    cudaGetSymbolAddress((void**)&q,  g_q);
    cudaGetSymbolAddress((void**)&k,  g_k);
    cudaGetSymbolAddress((void**)&v,  g_v);
    cudaGetSymbolAddress((void**)&ao, g_ao);
    cudaGetSymbolAddress((void**)&s,  g_s);
    cudaGetSymbolAddress((void**)&ff, g_ff);

    const int nElem = Mrows * Dc;                 // 4M
    copy4_kernel<<<(nElem / 4 + 255) / 256, 256>>>((float4*)x, (const float4*)trg, nElem / 4);

    dim3 gProj(Dc / 64, Mrows / 64);              // (16,64)
    dim3 gFF1(FFc / 64, Mrows / 64);              // (64,64)
    dim3 gScore(Nc / 64, Nc / 64, Bc * Hc);       // (8,8,128)
    dim3 gPV(Nc / 64, Bc * Hc);                   // (8,128)
    const int nRowsS = Bc * Hc * Nc;              // 65536

    for (int l = 0; l < Lc; l++) {
        const size_t wOff = (size_t)l * 4 * Dc * Dc;
        const size_t bOff = (size_t)l * 4 * Dc;
        const float* Ws = sa_w + wOff;
        const float* Bs = sa_b + bOff;
        const float* Wc = ca_w + wOff;
        const float* Bcp = ca_b + bOff;

        // ---- self-attention ----
        gemm_bias_kernel<false><<<gProj, 256>>>(x, Ws + 0 * Dc * Dc, Bs + 0 * Dc, q, Mrows, Dc, Dc);
        gemm_bias_kernel<false><<<gProj, 256>>>(x, Ws + 1 * Dc * Dc, Bs + 1 * Dc, k, Mrows, Dc, Dc);
        gemm_bias_kernel<false><<<gProj, 256>>>(x, Ws + 2 * Dc * Dc, Bs + 2 * Dc, v, Mrows, Dc, Dc);
        attn_scores_kernel<<<gScore, 256>>>(q, k, mask, s, 1);
        softmax512_kernel<<<nRowsS, 256>>>(s);
        attn_pv_kernel<<<gPV, 256>>>(s, v, ao);
        gemm_bias_kernel<false><<<gProj, 256>>>(ao, Ws + 3 * Dc * Dc, Bs + 3 * Dc, t, Mrows, Dc, Dc);
        add_ln_kernel<<<Mrows, 256>>>(t, x, ln_g + ((size_t)l * 3 + 0) * Dc, ln_b + ((size_t)l * 3 + 0) * Dc, x);

        // ---- cross-attention (K,V from enc; no mask) ----
        gemm_bias_kernel<false><<<gProj, 256>>>(x,   Wc + 0 * Dc * Dc, Bcp + 0 * Dc, q, Mrows, Dc, Dc);
        gemm_bias_kernel<false><<<gProj, 256>>>(enc, Wc + 1 * Dc * Dc, Bcp + 1 * Dc, k, Mrows, Dc, Dc);
        gemm_bias_kernel<false><<<gProj, 256>>>(enc, Wc + 2 * Dc * Dc, Bcp + 2 * Dc, v, Mrows, Dc, Dc);
        attn_scores_kernel<<<gScore, 256>>>(q, k, mask, s, 0);
        softmax512_kernel<<<nRowsS, 256>>>(s);
        attn_pv_kernel<<<gPV, 256>>>(s, v, ao);
        gemm_bias_kernel<false><<<gProj, 256>>>(ao, Wc + 3 * Dc * Dc, Bcp + 3 * Dc, t, Mrows, Dc, Dc);
        add_ln_kernel<<<Mrows, 256>>>(t, x, ln_g + ((size_t)l * 3 + 1) * Dc, ln_b + ((size_t)l * 3 + 1) * Dc, x);

        // ---- FFN ----
        gemm_bias_kernel<true><<<gFF1, 256>>>(x, w1 + (size_t)l * Dc * FFc, b1 + (size_t)l * FFc, ff, Mrows, FFc, Dc);
        gemm_bias_kernel<false><<<gProj, 256>>>(ff, w2 + (size_t)l * FFc * Dc, b2 + (size_t)l * Dc, t, Mrows, Dc, FFc);
        add_ln_kernel<<<Mrows, 256>>>(t, x, ln_g + ((size_t)l * 3 + 2) * Dc, ln_b + ((size_t)l * 3 + 2) * Dc, x);
    }

    copy4_kernel<<<(nElem / 4 + 255) / 256, 256>>>((float4*)out, (const float4*)x, nElem / 4);
}

// round 3
// speedup vs baseline: 3.1870x; 3.1870x over previous
#include <cuda_runtime.h>
#include <cuda_fp16.h>
#include <math.h>
#include <stdint.h>

// Problem constants
#define Lc   6
#define Dc   1024
#define Hc   16
#define DHc  64
#define FFc  4096
#define Bc   8
#define Nc   512
#define Mrows (Bc*Nc)          // 4096
#define EPSc 1e-12f

// ------------------------------------------------------------------
// Scratch (device globals; allocation is forbidden in kernel_launch)
// ------------------------------------------------------------------
__device__ float g_x [Mrows*Dc];
__device__ float g_t [Mrows*Dc];
__device__ float g_q [Mrows*Dc];
__device__ float g_k [Mrows*Dc];
__device__ float g_v [Mrows*Dc];
__device__ float g_ao[Mrows*Dc];
__device__ float g_s [(size_t)Bc*Hc*Nc*Nc];   // 134 MB scores
__device__ float g_ff[(size_t)Mrows*FFc];     // 67 MB ffn hidden

// fp16 operand buffers
__device__ __half g_a16[(size_t)Mrows*FFc];   // activations (up to 4096x4096)
__device__ __half g_b16[(size_t)FFc*Dc];      // weight^T (up to 4096x1024)
__device__ __half g_e16[(size_t)Mrows*Dc];    // enc (converted once)

// ------------------------------------------------------------------
// PTX helpers
// ------------------------------------------------------------------
__device__ __forceinline__ uint32_t smem_u32(const void* p) {
    uint32_t a;
    asm("{ .reg .u64 t; cvta.to.shared.u64 t, %1; cvt.u32.u64 %0, t; }" : "=r"(a) : "l"(p));
    return a;
}

__device__ __forceinline__ void cp16(uint32_t dst, const void* src) {
    asm volatile("cp.async.cg.shared.global [%0], [%1], 16;" :: "r"(dst), "l"(src) : "memory");
}
#define CP_COMMIT() asm volatile("cp.async.commit_group;" ::: "memory")

__device__ __forceinline__ void ldsm4(uint32_t& r0, uint32_t& r1, uint32_t& r2, uint32_t& r3, uint32_t addr) {
    asm volatile("ldmatrix.sync.aligned.m8n8.x4.shared.b16 {%0,%1,%2,%3}, [%4];"
        : "=r"(r0), "=r"(r1), "=r"(r2), "=r"(r3) : "r"(addr));
}

__device__ __forceinline__ void mma16816(float* c, const uint32_t* a, uint32_t b0, uint32_t b1) {
    asm volatile(
        "mma.sync.aligned.m16n8k16.row.col.f32.f16.f16.f32 "
        "{%0,%1,%2,%3}, {%4,%5,%6,%7}, {%8,%9}, {%0,%1,%2,%3};"
        : "+f"(c[0]), "+f"(c[1]), "+f"(c[2]), "+f"(c[3])
        : "r"(a[0]), "r"(a[1]), "r"(a[2]), "r"(a[3]), "r"(b0), "r"(b1));
}

// ------------------------------------------------------------------
// fp16 mma GEMM: C[M,N] = A[M,K]h @ Bt[N,K]h^T + bias  (+ optional ReLU)
// BM=128, BN=128, BK=32, 4 stages cp.async, 256 threads (8 warps 4x2).
// smem per stage: A 128 rows x 80B + B 128 x 80B = 20480B; total 81920B.
// Requires M%128==0, N%128==0, K%32==0.
// ------------------------------------------------------------------
#define GEMM_SMEM (4 * 20480)

__device__ __forceinline__ void cp_stage_g(uint32_t sbase,
    const __half* __restrict__ A, const __half* __restrict__ B,
    int m0, int n0, int k0, int K, int tid)
{
#pragma unroll
    for (int j = 0; j < 2; j++) {
        int id = tid + 256 * j;          // 0..511
        int row = id >> 2;               // 0..127
        int c = id & 3;                  // 0..3
        uint32_t d = (uint32_t)(row * 80 + c * 16);
        cp16(sbase + d,         A + (size_t)(m0 + row) * K + k0 + c * 8);
        cp16(sbase + 10240 + d, B + (size_t)(n0 + row) * K + k0 + c * 8);
    }
}

template<bool RELU>
__global__ void __launch_bounds__(256, 2)
gemm_mma_kernel(const __half* __restrict__ A, const __half* __restrict__ B,
                const float* __restrict__ bias, float* __restrict__ C,
                int M, int N, int K)
{
    extern __shared__ char sm_[];
    const uint32_t sb = smem_u32(sm_);
    const int tid = threadIdx.x;
    const int wid = tid >> 5;
    const int l = tid & 31;
    const int m0 = blockIdx.y * 128;
    const int n0 = blockIdx.x * 128;
    const int wm = (wid >> 1) * 32;      // warp M offset in tile
    const int wn = (wid & 1) * 64;       // warp N offset in tile
    const int KT = K >> 5;

    float c[2][8][4];
#pragma unroll
    for (int i = 0; i < 2; i++)
#pragma unroll
        for (int j = 0; j < 8; j++)
#pragma unroll
            for (int r = 0; r < 4; r++) c[i][j][r] = 0.f;

    // prologue: stages 0..2
#pragma unroll
    for (int s = 0; s < 3; s++) {
        cp_stage_g(sb + s * 20480, A, B, m0, n0, s * 32, K, tid);
        CP_COMMIT();
    }

    // lane-invariant ldmatrix offsets
    const uint32_t aoff = (uint32_t)((wm + (l & 15)) * 80 + (l >> 4) * 16);
    const uint32_t boff = (uint32_t)((wn + (l & 7) + ((l >> 3) & 1) * 8) * 80 + (l >> 4) * 16);

    for (int kt = 0; kt < KT; kt++) {
        asm volatile("cp.async.wait_group 2;" ::: "memory");
        __syncthreads();

        const int pf = kt + 3;
        if (pf < KT) cp_stage_g(sb + (pf & 3) * 20480, A, B, m0, n0, pf * 32, K, tid);
        CP_COMMIT();

        const uint32_t sA = sb + (kt & 3) * 20480;
        const uint32_t sB = sA + 10240;

#pragma unroll
        for (int kk = 0; kk < 2; kk++) {
            uint32_t a[2][4], b[4][4];
            ldsm4(a[0][0], a[0][1], a[0][2], a[0][3], sA + aoff + kk * 32);
            ldsm4(a[1][0], a[1][1], a[1][2], a[1][3], sA + aoff + 16 * 80 + kk * 32);
#pragma unroll
            for (int j = 0; j < 4; j++)
                ldsm4(b[j][0], b[j][1], b[j][2], b[j][3], sB + boff + j * 16 * 80 + kk * 32);
#pragma unroll
            for (int mi = 0; mi < 2; mi++)
#pragma unroll
                for (int nj = 0; nj < 8; nj++)
                    mma16816(c[mi][nj], a[mi], b[nj >> 1][nj & 1], b[nj >> 1][(nj & 1) + 2]);
        }
    }

    // epilogue
    const int row0 = m0 + wm + (l >> 2);
    const int colb = n0 + wn + (l & 3) * 2;
#pragma unroll
    for (int mi = 0; mi < 2; mi++) {
#pragma unroll
        for (int nj = 0; nj < 8; nj++) {
            const int col = colb + nj * 8;
            const float b0 = bias[col], b1 = bias[col + 1];
            float v0 = c[mi][nj][0] + b0;
            float v1 = c[mi][nj][1] + b1;
            float v2 = c[mi][nj][2] + b0;
            float v3 = c[mi][nj][3] + b1;
            if (RELU) {
                v0 = fmaxf(v0, 0.f); v1 = fmaxf(v1, 0.f);
                v2 = fmaxf(v2, 0.f); v3 = fmaxf(v3, 0.f);
            }
            const int r0 = row0 + mi * 16;
            float2 p0; p0.x = v0; p0.y = v1;
            float2 p1; p1.x = v2; p1.y = v3;
            *(float2*)&C[(size_t)r0 * N + col] = p0;
            *(float2*)&C[(size_t)(r0 + 8) * N + col] = p1;
        }
    }
}

// ------------------------------------------------------------------
// fp32 -> fp16 elementwise
// ------------------------------------------------------------------
__global__ void __launch_bounds__(256)
f2h_kernel(const float* __restrict__ in, __half* __restrict__ out, int n)
{
    int i = (blockIdx.x * 256 + threadIdx.x) * 4;
    if (i >= n) return;
    float4 v = *(const float4*)(in + i);
    *(__half2*)(out + i)     = __floats2half2_rn(v.x, v.y);
    *(__half2*)(out + i + 2) = __floats2half2_rn(v.z, v.w);
}

// ------------------------------------------------------------------
// Transpose + convert: W[K,N] fp32 -> Wt[N,K] fp16
// ------------------------------------------------------------------
__global__ void __launch_bounds__(256)
wt_kernel(const float* __restrict__ W, __half* __restrict__ T, int K, int N)
{
    __shared__ float t[32][33];
    const int n0 = blockIdx.x * 32;
    const int k0 = blockIdx.y * 32;
    const int tx = threadIdx.x;      // 0..31
    const int ty = threadIdx.y;      // 0..7
#pragma unroll
    for (int i = 0; i < 4; i++)
        t[ty + i * 8][tx] = W[(size_t)(k0 + ty + i * 8) * N + n0 + tx];
    __syncthreads();
#pragma unroll
    for (int i = 0; i < 4; i++) {
        T[(size_t)(n0 + ty + i * 8) * K + k0 + tx] = __float2half(t[tx][ty + i * 8]);
    }
}

// ------------------------------------------------------------------
// float4 copy
// ------------------------------------------------------------------
__global__ void copy4_kernel(float4* __restrict__ dst, const float4* __restrict__ src, int n4) {
    int i = blockIdx.x * blockDim.x + threadIdx.x;
    if (i < n4) dst[i] = src[i];
}

// ------------------------------------------------------------------
// Attention scores (fp32): S[b,h,q,k] = (Q.K)/8, masked
// ------------------------------------------------------------------
__global__ void __launch_bounds__(256)
attn_scores_kernel(const float* __restrict__ Q, const float* __restrict__ Kmat,
                   const int* __restrict__ mask, float* __restrict__ S, int useMask)
{
    const int bh = blockIdx.z;
    const int b = bh >> 4;
    const int h = bh & 15;
    const float* Qb = Q + (size_t)b * Nc * Dc + h * DHc;
    const float* Kb = Kmat + (size_t)b * Nc * Dc + h * DHc;
    float* Sb = S + (size_t)bh * Nc * Nc;

    const int q0 = blockIdx.y * 64;
    const int k0 = blockIdx.x * 64;
    const int tid = threadIdx.x;
    const int tx = tid & 15;
    const int ty = tid >> 4;

    __shared__ float Qs[64][65];
    __shared__ float Ks[64][65];

    for (int i = tid; i < 1024; i += 256) {
        int row = i >> 4;
        int dq = (i & 15) * 4;
        float4 a = *(const float4*)&Qb[(size_t)(q0 + row) * Dc + dq];
        Qs[row][dq + 0] = a.x; Qs[row][dq + 1] = a.y; Qs[row][dq + 2] = a.z; Qs[row][dq + 3] = a.w;
        float4 c = *(const float4*)&Kb[(size_t)(k0 + row) * Dc + dq];
        Ks[row][dq + 0] = c.x; Ks[row][dq + 1] = c.y; Ks[row][dq + 2] = c.z; Ks[row][dq + 3] = c.w;
    }
    __syncthreads();

    float acc[4][4];
#pragma unroll
    for (int i = 0; i < 4; i++)
#pragma unroll
        for (int j = 0; j < 4; j++) acc[i][j] = 0.f;

#pragma unroll 4
    for (int d = 0; d < 64; d++) {
        float ra[4], rb[4];
#pragma unroll
        for (int i = 0; i < 4; i++) ra[i] = Qs[ty * 4 + i][d];
#pragma unroll
        for (int j = 0; j < 4; j++) rb[j] = Ks[tx * 4 + j][d];
#pragma unroll
        for (int i = 0; i < 4; i++)
#pragma unroll
            for (int j = 0; j < 4; j++) acc[i][j] += ra[i] * rb[j];
    }

#pragma unroll
    for (int i = 0; i < 4; i++) {
        int qq = q0 + ty * 4 + i;
#pragma unroll
        for (int j = 0; j < 4; j++) {
            int kk = k0 + tx * 4 + j;
            float val = acc[i][j] * 0.125f;
            if (useMask) {
                if (mask[((size_t)b * Nc + qq) * Nc + kk] == 0) val = -10000.f;
            }
            Sb[(size_t)qq * Nc + kk] = val;
        }
    }
}

// ------------------------------------------------------------------
// Row softmax over 512
// ------------------------------------------------------------------
__global__ void __launch_bounds__(256)
softmax512_kernel(float* __restrict__ S)
{
    const size_t row = blockIdx.x;
    float* p = S + row * Nc;
    const int tid = threadIdx.x;

    float v0 = p[tid];
    float v1 = p[tid + 256];

    __shared__ float red[8];
    float m = fmaxf(v0, v1);
    for (int o = 16; o > 0; o >>= 1) m = fmaxf(m, __shfl_down_sync(0xffffffffu, m, o));
    if ((tid & 31) == 0) red[tid >> 5] = m;
    __syncthreads();
    if (tid < 32) {
        m = (tid < 8) ? red[tid] : -INFINITY;
        for (int o = 4; o > 0; o >>= 1) m = fmaxf(m, __shfl_down_sync(0xffffffffu, m, o));
        if (tid == 0) red[0] = m;
    }
    __syncthreads();
    m = red[0];
    __syncthreads();

    float e0 = expf(v0 - m);
    float e1 = expf(v1 - m);
    float s = e0 + e1;
    for (int o = 16; o > 0; o >>= 1) s += __shfl_down_sync(0xffffffffu, s, o);
    if ((tid & 31) == 0) red[tid >> 5] = s;
    __syncthreads();
    if (tid < 32) {
        s = (tid < 8) ? red[tid] : 0.f;
        for (int o = 4; o > 0; o >>= 1) s += __shfl_down_sync(0xffffffffu, s, o);
        if (tid == 0) red[0] = s;
    }
    __syncthreads();
    s = red[0];

    float inv = 1.f / s;
    p[tid] = e0 * inv;
    p[tid + 256] = e1 * inv;
}

// ------------------------------------------------------------------
// PV: O[b,q,h,:] = P[b,h,q,:] @ V[b,:,h,:]
// ------------------------------------------------------------------
__global__ void __launch_bounds__(256)
attn_pv_kernel(const float* __restrict__ S, const float* __restrict__ V, float* __restrict__ O)
{
    const int bh = blockIdx.y;
    const int b = bh >> 4;
    const int h = bh & 15;
    const float* Sb = S + (size_t)bh * Nc * Nc;
    const float* Vb = V + (size_t)b * Nc * Dc + h * DHc;
    float* Ob = O + (size_t)b * Nc * Dc + h * DHc;

    const int q0 = blockIdx.x * 64;
    const int tid = threadIdx.x;
    const int tx = tid & 15;
    const int ty = tid >> 4;

    __shared__ float Ps[64][33];
    __shared__ float Vs[32][64];

    float acc[4][4];
#pragma unroll
    for (int i = 0; i < 4; i++)
#pragma unroll
        for (int j = 0; j < 4; j++) acc[i][j] = 0.f;

    for (int kc = 0; kc < Nc; kc += 32) {
        for (int i = tid; i < 512; i += 256) {
            int row = i >> 3;
            int kq = (i & 7) * 4;
            float4 a = *(const float4*)&Sb[(size_t)(q0 + row) * Nc + kc + kq];
            Ps[row][kq + 0] = a.x; Ps[row][kq + 1] = a.y; Ps[row][kq + 2] = a.z; Ps[row][kq + 3] = a.w;
        }
        for (int i = tid; i < 512; i += 256) {
            int row = i >> 4;
            int nq = (i & 15) * 4;
            *(float4*)&Vs[row][nq] = *(const float4*)&Vb[(size_t)(kc + row) * Dc + nq];
        }
        __syncthreads();

#pragma unroll
        for (int kk = 0; kk < 32; kk++) {
            float ra[4];
#pragma unroll
            for (int i = 0; i < 4; i++) ra[i] = Ps[ty * 4 + i][kk];
            float4 rb = *(const float4*)&Vs[kk][tx * 4];
            acc[0][0] += ra[0] * rb.x; acc[0][1] += ra[0] * rb.y; acc[0][2] += ra[0] * rb.z; acc[0][3] += ra[0] * rb.w;
            acc[1][0] += ra[1] * rb.x; acc[1][1] += ra[1] * rb.y; acc[1][2] += ra[1] * rb.z; acc[1][3] += ra[1] * rb.w;
            acc[2][0] += ra[2] * rb.x; acc[2][1] += ra[2] * rb.y; acc[2][2] += ra[2] * rb.z; acc[2][3] += ra[2] * rb.w;
            acc[3][0] += ra[3] * rb.x; acc[3][1] += ra[3] * rb.y; acc[3][2] += ra[3] * rb.z; acc[3][3] += ra[3] * rb.w;
        }
        __syncthreads();
    }

#pragma unroll
    for (int i = 0; i < 4; i++) {
        int row = q0 + ty * 4 + i;
        float4 o;
        o.x = acc[i][0]; o.y = acc[i][1]; o.z = acc[i][2]; o.w = acc[i][3];
        *(float4*)&Ob[(size_t)row * Dc + tx * 4] = o;
    }
}

// ------------------------------------------------------------------
// Residual + LayerNorm
// ------------------------------------------------------------------
__global__ void __launch_bounds__(256)
add_ln_kernel(const float* __restrict__ A, const float* __restrict__ X,
              const float* __restrict__ gamma, const float* __restrict__ beta,
              float* __restrict__ out)
{
    const size_t row = blockIdx.x;
    const int tid = threadIdx.x;
    float vals[4];
    float s = 0.f, ss = 0.f;
#pragma unroll
    for (int i = 0; i < 4; i++) {
        int c = tid + i * 256;
        float v = A[row * Dc + c] + X[row * Dc + c];
        vals[i] = v;
        s += v;
        ss += v * v;
    }
    __shared__ float sa[8], sb_[8];
    int lane = tid & 31, w = tid >> 5;
    for (int o = 16; o > 0; o >>= 1) {
        s  += __shfl_down_sync(0xffffffffu, s, o);
        ss += __shfl_down_sync(0xffffffffu, ss, o);
    }
    if (lane == 0) { sa[w] = s; sb_[w] = ss; }
    __syncthreads();
    if (w == 0) {
        s  = (lane < 8) ? sa[lane] : 0.f;
        ss = (lane < 8) ? sb_[lane] : 0.f;
        for (int o = 4; o > 0; o >>= 1) {
            s  += __shfl_down_sync(0xffffffffu, s, o);
            ss += __shfl_down_sync(0xffffffffu, ss, o);
        }
        if (lane == 0) { sa[0] = s; sb_[0] = ss; }
    }
    __syncthreads();
    float mean = sa[0] * (1.f / Dc);
    float var = sb_[0] * (1.f / Dc) - mean * mean;
    float inv = rsqrtf(var + EPSc);
#pragma unroll
    for (int i = 0; i < 4; i++) {
        int c = tid + i * 256;
        out[row * Dc + c] = gamma[c] * (vals[i] - mean) * inv + beta[c];
    }
}

// ------------------------------------------------------------------
// Host orchestration
// ------------------------------------------------------------------
extern "C" void kernel_launch(void* const* d_in, const int* in_sizes, int n_in,
                              void* d_out, int out_size)
{
    const float* trg  = (const float*)d_in[0];
    const float* enc  = (const float*)d_in[1];
    const int*   mask = (const int*)  d_in[2];
    const float* sa_w = (const float*)d_in[3];
    const float* sa_b = (const float*)d_in[4];
    const float* ca_w = (const float*)d_in[5];
    const float* ca_b = (const float*)d_in[6];
    const float* ln_g = (const float*)d_in[7];
    const float* ln_b = (const float*)d_in[8];
    const float* w1   = (const float*)d_in[9];
    const float* b1   = (const float*)d_in[10];
    const float* w2   = (const float*)d_in[11];
    const float* b2   = (const float*)d_in[12];
    float* out = (float*)d_out;

    float *x, *t, *q, *k, *v, *ao, *s, *ff;
    __half *a16, *b16, *e16;
    cudaGetSymbolAddress((void**)&x,  g_x);
    cudaGetSymbolAddress((void**)&t,  g_t);
    cudaGetSymbolAddress((void**)&q,  g_q);
    cudaGetSymbolAddress((void**)&k,  g_k);
    cudaGetSymbolAddress((void**)&v,  g_v);
    cudaGetSymbolAddress((void**)&ao, g_ao);
    cudaGetSymbolAddress((void**)&s,  g_s);
    cudaGetSymbolAddress((void**)&ff, g_ff);
    cudaGetSymbolAddress((void**)&a16, g_a16);
    cudaGetSymbolAddress((void**)&b16, g_b16);
    cudaGetSymbolAddress((void**)&e16, g_e16);

    cudaFuncSetAttribute(gemm_mma_kernel<false>, cudaFuncAttributeMaxDynamicSharedMemorySize, GEMM_SMEM);
    cudaFuncSetAttribute(gemm_mma_kernel<true>,  cudaFuncAttributeMaxDynamicSharedMemorySize, GEMM_SMEM);

    const int nElem = Mrows * Dc;               // 4M
    const int nFF = Mrows * FFc;                // 16.7M
    copy4_kernel<<<(nElem / 4 + 255) / 256, 256>>>((float4*)x, (const float4*)trg, nElem / 4);
    f2h_kernel<<<(nElem / 4 + 255) / 256, 256>>>(enc, e16, nElem);

    dim3 gProj(Dc / 128, Mrows / 128);          // (8, 32)
    dim3 gFF1(FFc / 128, Mrows / 128);          // (32, 32)
    dim3 gScore(Nc / 64, Nc / 64, Bc * Hc);
    dim3 gPV(Nc / 64, Bc * Hc);
    const int nRowsS = Bc * Hc * Nc;

    dim3 wtBlk(32, 8);
    dim3 gWtProj(Dc / 32, Dc / 32);             // [1024,1024]
    dim3 gWtW1(FFc / 32, Dc / 32);              // W1 [1024,4096] -> [4096,1024]
    dim3 gWtW2(Dc / 32, FFc / 32);              // W2 [4096,1024] -> [1024,4096]

    const int cvX  = (nElem / 4 + 255) / 256;
    const int cvFF = (nFF / 4 + 255) / 256;

    for (int l = 0; l < Lc; l++) {
        const size_t wOff = (size_t)l * 4 * Dc * Dc;
        const size_t bOff = (size_t)l * 4 * Dc;
        const float* Ws = sa_w + wOff;
        const float* Bs = sa_b + bOff;
        const float* Wc = ca_w + wOff;
        const float* Bcp = ca_b + bOff;

        // ================= self-attention =================
        f2h_kernel<<<cvX, 256>>>(x, a16, nElem);

        wt_kernel<<<gWtProj, wtBlk>>>(Ws + 0 * Dc * Dc, b16, Dc, Dc);
        gemm_mma_kernel<false><<<gProj, 256, GEMM_SMEM>>>(a16, b16, Bs + 0 * Dc, q, Mrows, Dc, Dc);
        wt_kernel<<<gWtProj, wtBlk>>>(Ws + 1 * Dc * Dc, b16, Dc, Dc);
        gemm_mma_kernel<false><<<gProj, 256, GEMM_SMEM>>>(a16, b16, Bs + 1 * Dc, k, Mrows, Dc, Dc);
        wt_kernel<<<gWtProj, wtBlk>>>(Ws + 2 * Dc * Dc, b16, Dc, Dc);
        gemm_mma_kernel<false><<<gProj, 256, GEMM_SMEM>>>(a16, b16, Bs + 2 * Dc, v, Mrows, Dc, Dc);

        attn_scores_kernel<<<gScore, 256>>>(q, k, mask, s, 1);
        softmax512_kernel<<<nRowsS, 256>>>(s);
        attn_pv_kernel<<<gPV, 256>>>(s, v, ao);

        f2h_kernel<<<cvX, 256>>>(ao, a16, nElem);
        wt_kernel<<<gWtProj, wtBlk>>>(Ws + 3 * Dc * Dc, b16, Dc, Dc);
        gemm_mma_kernel<false><<<gProj, 256, GEMM_SMEM>>>(a16, b16, Bs + 3 * Dc, t, Mrows, Dc, Dc);
        add_ln_kernel<<<Mrows, 256>>>(t, x, ln_g + ((size_t)l * 3 + 0) * Dc, ln_b + ((size_t)l * 3 + 0) * Dc, x);

        // ================= cross-attention =================
        f2h_kernel<<<cvX, 256>>>(x, a16, nElem);
        wt_kernel<<<gWtProj, wtBlk>>>(Wc + 0 * Dc * Dc, b16, Dc, Dc);
        gemm_mma_kernel<false><<<gProj, 256, GEMM_SMEM>>>(a16, b16, Bcp + 0 * Dc, q, Mrows, Dc, Dc);
        wt_kernel<<<gWtProj, wtBlk>>>(Wc + 1 * Dc * Dc, b16, Dc, Dc);
        gemm_mma_kernel<false><<<gProj, 256, GEMM_SMEM>>>(e16, b16, Bcp + 1 * Dc, k, Mrows, Dc, Dc);
        wt_kernel<<<gWtProj, wtBlk>>>(Wc + 2 * Dc * Dc, b16, Dc, Dc);
        gemm_mma_kernel<false><<<gProj, 256, GEMM_SMEM>>>(e16, b16, Bcp + 2 * Dc, v, Mrows, Dc, Dc);

        attn_scores_kernel<<<gScore, 256>>>(q, k, mask, s, 0);
        softmax512_kernel<<<nRowsS, 256>>>(s);
        attn_pv_kernel<<<gPV, 256>>>(s, v, ao);

        f2h_kernel<<<cvX, 256>>>(ao, a16, nElem);
        wt_kernel<<<gWtProj, wtBlk>>>(Wc + 3 * Dc * Dc, b16, Dc, Dc);
        gemm_mma_kernel<false><<<gProj, 256, GEMM_SMEM>>>(a16, b16, Bcp + 3 * Dc, t, Mrows, Dc, Dc);
        add_ln_kernel<<<Mrows, 256>>>(t, x, ln_g + ((size_t)l * 3 + 1) * Dc, ln_b + ((size_t)l * 3 + 1) * Dc, x);

        // ================= FFN =================
        f2h_kernel<<<cvX, 256>>>(x, a16, nElem);
        wt_kernel<<<gWtW1, wtBlk>>>(w1 + (size_t)l * Dc * FFc, b16, Dc, FFc);
        gemm_mma_kernel<true><<<gFF1, 256, GEMM_SMEM>>>(a16, b16, b1 + (size_t)l * FFc, ff, Mrows, FFc, Dc);

        f2h_kernel<<<cvFF, 256>>>(ff, a16, nFF);
        wt_kernel<<<gWtW2, wtBlk>>>(w2 + (size_t)l * FFc * Dc, b16, FFc, Dc);
        gemm_mma_kernel<false><<<gProj, 256, GEMM_SMEM>>>(a16, b16, b2 + (size_t)l * Dc, t, Mrows, Dc, FFc);

        add_ln_kernel<<<Mrows, 256>>>(t, x, ln_g + ((size_t)l * 3 + 2) * Dc, ln_b + ((size_t)l * 3 + 2) * Dc, x);
    }

    copy4_kernel<<<(nElem / 4 + 255) / 256, 256>>>((float4*)out, (const float4*)x, nElem / 4);
}

// round 5
// speedup vs baseline: 5.1420x; 1.6135x over previous
#include <cuda_runtime.h>
#include <cuda_fp16.h>
#include <math.h>
#include <stdint.h>

// Problem constants
#define Lc   6
#define Dc   1024
#define Hc   16
#define DHc  64
#define FFc  4096
#define Bc   8
#define Nc   512
#define Mrows (Bc*Nc)          // 4096
#define EPSc 1e-12f

// ------------------------------------------------------------------
// Scratch (device globals)
// ------------------------------------------------------------------
__device__ float g_x [Mrows*Dc];
__device__ float g_t [Mrows*Dc];
__device__ float g_s [(size_t)Bc*Hc*Nc*Nc];     // 134 MB fp32 scores

__device__ __half g_x16[Mrows*Dc];
__device__ __half g_e16[Mrows*Dc];
__device__ __half g_q16[Mrows*Dc];
__device__ __half g_k16[Mrows*Dc];
__device__ __half g_v16[Mrows*Dc];
__device__ __half g_vt16[Mrows*Dc];             // [bh][dh=64][kv=512]
__device__ __half g_ao16[Mrows*Dc];
__device__ __half g_ff16[(size_t)Mrows*FFc];
__device__ __half g_p16[(size_t)Bc*Hc*Nc*Nc];   // 67 MB fp16 probs

// transposed fp16 weights (built once per launch)
__device__ __half g_wsa[(size_t)Lc*4*Dc*Dc];
__device__ __half g_wca[(size_t)Lc*4*Dc*Dc];
__device__ __half g_w1t[(size_t)Lc*Dc*FFc];
__device__ __half g_w2t[(size_t)Lc*FFc*Dc];

// ------------------------------------------------------------------
// PTX helpers
// ------------------------------------------------------------------
__device__ __forceinline__ uint32_t smem_u32(const void* p) {
    uint32_t a;
    asm("{ .reg .u64 t; cvta.to.shared.u64 t, %1; cvt.u32.u64 %0, t; }" : "=r"(a) : "l"(p));
    return a;
}
__device__ __forceinline__ void cp16(uint32_t dst, const void* src) {
    asm volatile("cp.async.cg.shared.global [%0], [%1], 16;" :: "r"(dst), "l"(src) : "memory");
}
#define CP_COMMIT() asm volatile("cp.async.commit_group;" ::: "memory")

__device__ __forceinline__ void ldsm4(uint32_t& r0, uint32_t& r1, uint32_t& r2, uint32_t& r3, uint32_t addr) {
    asm volatile("ldmatrix.sync.aligned.m8n8.x4.shared.b16 {%0,%1,%2,%3}, [%4];"
        : "=r"(r0), "=r"(r1), "=r"(r2), "=r"(r3) : "r"(addr));
}
__device__ __forceinline__ void mma16816(float* c, const uint32_t* a, uint32_t b0, uint32_t b1) {
    asm volatile(
        "mma.sync.aligned.m16n8k16.row.col.f32.f16.f16.f32 "
        "{%0,%1,%2,%3}, {%4,%5,%6,%7}, {%8,%9}, {%0,%1,%2,%3};"
        : "+f"(c[0]), "+f"(c[1]), "+f"(c[2]), "+f"(c[3])
        : "r"(a[0]), "r"(a[1]), "r"(a[2]), "r"(a[3]), "r"(b0), "r"(b1));
}

// ==================================================================
// Dense GEMM: C[M,N] = A[M,K] @ Bt[N,K]^T + bias (+ReLU). fp16 or fp32 out.
// BM=128, BN=128, BK=32, 4-stage cp.async, 256 threads (8 warps 4x2).
// ==================================================================
#define GEMM_SMEM (4 * 20480)

__device__ __forceinline__ void cp_stage_g(uint32_t sbase,
    const __half* __restrict__ A, const __half* __restrict__ B,
    int m0, int n0, int k0, int K, int tid)
{
#pragma unroll
    for (int j = 0; j < 2; j++) {
        int id = tid + 256 * j;
        int row = id >> 2;
        int c = id & 3;
        uint32_t d = (uint32_t)(row * 80 + c * 16);
        cp16(sbase + d,         A + (size_t)(m0 + row) * K + k0 + c * 8);
        cp16(sbase + 10240 + d, B + (size_t)(n0 + row) * K + k0 + c * 8);
    }
}

template<bool RELU, bool HOUT>
__global__ void __launch_bounds__(256, 2)
gemm_mma_kernel(const __half* __restrict__ A, const __half* __restrict__ B,
                const float* __restrict__ bias, void* __restrict__ Cout,
                int M, int N, int K)
{
    extern __shared__ char sm_[];
    const uint32_t sb = smem_u32(sm_);
    const int tid = threadIdx.x;
    const int wid = tid >> 5;
    const int l = tid & 31;
    const int m0 = blockIdx.y * 128;
    const int n0 = blockIdx.x * 128;
    const int wm = (wid >> 1) * 32;
    const int wn = (wid & 1) * 64;
    const int KT = K >> 5;

    float c[2][8][4];
#pragma unroll
    for (int i = 0; i < 2; i++)
#pragma unroll
        for (int j = 0; j < 8; j++)
#pragma unroll
            for (int r = 0; r < 4; r++) c[i][j][r] = 0.f;

#pragma unroll
    for (int s = 0; s < 3; s++) {
        cp_stage_g(sb + s * 20480, A, B, m0, n0, s * 32, K, tid);
        CP_COMMIT();
    }

    const uint32_t aoff = (uint32_t)((wm + (l & 15)) * 80 + (l >> 4) * 16);
    const uint32_t boff = (uint32_t)((wn + (l & 7) + ((l >> 3) & 1) * 8) * 80 + (l >> 4) * 16);

    for (int kt = 0; kt < KT; kt++) {
        asm volatile("cp.async.wait_group 2;" ::: "memory");
        __syncthreads();

        const int pf = kt + 3;
        if (pf < KT) cp_stage_g(sb + (pf & 3) * 20480, A, B, m0, n0, pf * 32, K, tid);
        CP_COMMIT();

        const uint32_t sA = sb + (kt & 3) * 20480;
        const uint32_t sB = sA + 10240;

#pragma unroll
        for (int kk = 0; kk < 2; kk++) {
            uint32_t a[2][4], b[4][4];
            ldsm4(a[0][0], a[0][1], a[0][2], a[0][3], sA + aoff + kk * 32);
            ldsm4(a[1][0], a[1][1], a[1][2], a[1][3], sA + aoff + 16 * 80 + kk * 32);
#pragma unroll
            for (int j = 0; j < 4; j++)
                ldsm4(b[j][0], b[j][1], b[j][2], b[j][3], sB + boff + j * 16 * 80 + kk * 32);
#pragma unroll
            for (int mi = 0; mi < 2; mi++)
#pragma unroll
                for (int nj = 0; nj < 8; nj++)
                    mma16816(c[mi][nj], a[mi], b[nj >> 1][nj & 1], b[nj >> 1][(nj & 1) + 2]);
        }
    }

    const int row0 = m0 + wm + (l >> 2);
    const int colb = n0 + wn + (l & 3) * 2;
#pragma unroll
    for (int mi = 0; mi < 2; mi++) {
#pragma unroll
        for (int nj = 0; nj < 8; nj++) {
            const int col = colb + nj * 8;
            const float b0 = bias[col], b1 = bias[col + 1];
            float v0 = c[mi][nj][0] + b0;
            float v1 = c[mi][nj][1] + b1;
            float v2 = c[mi][nj][2] + b0;
            float v3 = c[mi][nj][3] + b1;
            if (RELU) {
                v0 = fmaxf(v0, 0.f); v1 = fmaxf(v1, 0.f);
                v2 = fmaxf(v2, 0.f); v3 = fmaxf(v3, 0.f);
            }
            const int r0 = row0 + mi * 16;
            if (HOUT) {
                __half* C = (__half*)Cout;
                *(__half2*)&C[(size_t)r0 * N + col]       = __floats2half2_rn(v0, v1);
                *(__half2*)&C[(size_t)(r0 + 8) * N + col] = __floats2half2_rn(v2, v3);
            } else {
                float* C = (float*)Cout;
                float2 p0; p0.x = v0; p0.y = v1;
                float2 p1; p1.x = v2; p1.y = v3;
                *(float2*)&C[(size_t)r0 * N + col] = p0;
                *(float2*)&C[(size_t)(r0 + 8) * N + col] = p1;
            }
        }
    }
}

// ==================================================================
// Attention scores: S = (Q @ K^T)/8 (+mask). fp16 in, fp32 out.
// ==================================================================
#define SCORE_SMEM (2 * 20480)

__global__ void __launch_bounds__(256, 2)
scores_mma_kernel(const __half* __restrict__ Q, const __half* __restrict__ Km,
                  const int* __restrict__ mask, float* __restrict__ S, int useMask)
{
    extern __shared__ char sm_[];
    const uint32_t sb = smem_u32(sm_);
    const int tid = threadIdx.x;
    const int wid = tid >> 5;
    const int l = tid & 31;
    const int bh = blockIdx.z;
    const int b = bh >> 4;
    const int h = bh & 15;
    const int q0 = blockIdx.y * 128;
    const int k0b = blockIdx.x * 128;

    const __half* Qb = Q + (size_t)b * Nc * Dc + h * DHc;
    const __half* Kb = Km + (size_t)b * Nc * Dc + h * DHc;
    float* Sb = S + (size_t)bh * Nc * Nc;

    const int wm = (wid >> 1) * 32;
    const int wn = (wid & 1) * 64;

#pragma unroll
    for (int s = 0; s < 2; s++) {
        uint32_t sbase = sb + s * 20480;
#pragma unroll
        for (int j = 0; j < 2; j++) {
            int id = tid + 256 * j;
            int row = id >> 2;
            int c = id & 3;
            uint32_t d = (uint32_t)(row * 80 + c * 16);
            cp16(sbase + d,         Qb + (size_t)(q0 + row) * Dc + s * 32 + c * 8);
            cp16(sbase + 10240 + d, Kb + (size_t)(k0b + row) * Dc + s * 32 + c * 8);
        }
        CP_COMMIT();
    }

    float c[2][8][4];
#pragma unroll
    for (int i = 0; i < 2; i++)
#pragma unroll
        for (int j = 0; j < 8; j++)
#pragma unroll
            for (int r = 0; r < 4; r++) c[i][j][r] = 0.f;

    const uint32_t aoff = (uint32_t)((wm + (l & 15)) * 80 + (l >> 4) * 16);
    const uint32_t boff = (uint32_t)((wn + (l & 7) + ((l >> 3) & 1) * 8) * 80 + (l >> 4) * 16);

    asm volatile("cp.async.wait_group 0;" ::: "memory");
    __syncthreads();

#pragma unroll
    for (int kt = 0; kt < 2; kt++) {
        const uint32_t sA = sb + kt * 20480;
        const uint32_t sB = sA + 10240;
#pragma unroll
        for (int kk = 0; kk < 2; kk++) {
            uint32_t a[2][4], bfr[4][4];
            ldsm4(a[0][0], a[0][1], a[0][2], a[0][3], sA + aoff + kk * 32);
            ldsm4(a[1][0], a[1][1], a[1][2], a[1][3], sA + aoff + 16 * 80 + kk * 32);
#pragma unroll
            for (int j = 0; j < 4; j++)
                ldsm4(bfr[j][0], bfr[j][1], bfr[j][2], bfr[j][3], sB + boff + j * 16 * 80 + kk * 32);
#pragma unroll
            for (int mi = 0; mi < 2; mi++)
#pragma unroll
                for (int nj = 0; nj < 8; nj++)
                    mma16816(c[mi][nj], a[mi], bfr[nj >> 1][nj & 1], bfr[nj >> 1][(nj & 1) + 2]);
        }
    }

    const int row0 = q0 + wm + (l >> 2);
    const int colb = k0b + wn + (l & 3) * 2;
#pragma unroll
    for (int mi = 0; mi < 2; mi++) {
#pragma unroll
        for (int nj = 0; nj < 8; nj++) {
            const int col = colb + nj * 8;
            float v0 = c[mi][nj][0] * 0.125f;
            float v1 = c[mi][nj][1] * 0.125f;
            float v2 = c[mi][nj][2] * 0.125f;
            float v3 = c[mi][nj][3] * 0.125f;
            const int r0 = row0 + mi * 16;
            if (useMask) {
                const int* m0p = &mask[((size_t)b * Nc + r0) * Nc + col];
                const int* m1p = &mask[((size_t)b * Nc + r0 + 8) * Nc + col];
                if (m0p[0] == 0) v0 = -10000.f;
                if (m0p[1] == 0) v1 = -10000.f;
                if (m1p[0] == 0) v2 = -10000.f;
                if (m1p[1] == 0) v3 = -10000.f;
            }
            float2 p0; p0.x = v0; p0.y = v1;
            float2 p1; p1.x = v2; p1.y = v3;
            *(float2*)&Sb[(size_t)r0 * Nc + col] = p0;
            *(float2*)&Sb[(size_t)(r0 + 8) * Nc + col] = p1;
        }
    }
}

// ==================================================================
// PV: O[q,dh] = P[q,kv] @ VT[dh,kv]^T. fp16 in/out. BM=128,BN=64,BK=32.
// ==================================================================
#define PV_SMEM (4 * 15360)

__device__ __forceinline__ void cp_stage_pv(uint32_t sbase,
    const __half* __restrict__ P, const __half* __restrict__ VT,
    int q0, int k0, int tid)
{
#pragma unroll
    for (int j = 0; j < 2; j++) {
        int id = tid + 256 * j;
        int row = id >> 2;
        int c = id & 3;
        cp16(sbase + (uint32_t)(row * 80 + c * 16),
             P + (size_t)(q0 + row) * Nc + k0 + c * 8);
    }
    {
        int row = tid >> 2;
        int c = tid & 3;
        cp16(sbase + 10240 + (uint32_t)(row * 80 + c * 16),
             VT + (size_t)row * Nc + k0 + c * 8);
    }
}

__global__ void __launch_bounds__(256, 2)
pv_mma_kernel(const __half* __restrict__ P, const __half* __restrict__ VT,
              __half* __restrict__ O)
{
    extern __shared__ char sm_[];
    const uint32_t sb = smem_u32(sm_);
    const int tid = threadIdx.x;
    const int wid = tid >> 5;
    const int l = tid & 31;
    const int bh = blockIdx.y;
    const int b = bh >> 4;
    const int h = bh & 15;
    const int q0 = blockIdx.x * 128;

    const __half* Pb = P + (size_t)bh * Nc * Nc;
    const __half* VTb = VT + (size_t)bh * DHc * Nc;

    const int wm = (wid >> 1) * 32;
    const int wn = (wid & 1) * 32;
    const int KT = Nc >> 5;   // 16

    float c[2][4][4];
#pragma unroll
    for (int i = 0; i < 2; i++)
#pragma unroll
        for (int j = 0; j < 4; j++)
#pragma unroll
            for (int r = 0; r < 4; r++) c[i][j][r] = 0.f;

#pragma unroll
    for (int s = 0; s < 3; s++) {
        cp_stage_pv(sb + s * 15360, Pb, VTb, q0, s * 32, tid);
        CP_COMMIT();
    }

    const uint32_t aoff = (uint32_t)((wm + (l & 15)) * 80 + (l >> 4) * 16);
    const uint32_t boff = (uint32_t)((wn + (l & 7) + ((l >> 3) & 1) * 8) * 80 + (l >> 4) * 16);

    for (int kt = 0; kt < KT; kt++) {
        asm volatile("cp.async.wait_group 2;" ::: "memory");
        __syncthreads();

        const int pf = kt + 3;
        if (pf < KT) cp_stage_pv(sb + (pf & 3) * 15360, Pb, VTb, q0, pf * 32, tid);
        CP_COMMIT();

        const uint32_t sA = sb + (kt & 3) * 15360;
        const uint32_t sB = sA + 10240;

#pragma unroll
        for (int kk = 0; kk < 2; kk++) {
            uint32_t a[2][4], bfr[2][4];
            ldsm4(a[0][0], a[0][1], a[0][2], a[0][3], sA + aoff + kk * 32);
            ldsm4(a[1][0], a[1][1], a[1][2], a[1][3], sA + aoff + 16 * 80 + kk * 32);
#pragma unroll
            for (int j = 0; j < 2; j++)
                ldsm4(bfr[j][0], bfr[j][1], bfr[j][2], bfr[j][3], sB + boff + j * 16 * 80 + kk * 32);
#pragma unroll
            for (int mi = 0; mi < 2; mi++)
#pragma unroll
                for (int nj = 0; nj < 4; nj++)
                    mma16816(c[mi][nj], a[mi], bfr[nj >> 1][nj & 1], bfr[nj >> 1][(nj & 1) + 2]);
        }
    }

    const int row0 = q0 + wm + (l >> 2);
    const int colb = wn + (l & 3) * 2;
#pragma unroll
    for (int mi = 0; mi < 2; mi++) {
#pragma unroll
        for (int nj = 0; nj < 4; nj++) {
            const int gc = h * DHc + colb + nj * 8;
            const int r0 = row0 + mi * 16;
            *(__half2*)&O[(size_t)(b * Nc + r0) * Dc + gc] =
                __floats2half2_rn(c[mi][nj][0], c[mi][nj][1]);
            *(__half2*)&O[(size_t)(b * Nc + r0 + 8) * Dc + gc] =
                __floats2half2_rn(c[mi][nj][2], c[mi][nj][3]);
        }
    }
}

// ==================================================================
// V transpose: v16[b][kv][h*64+dh] -> vt16[bh][dh][kv]
// Tile: 32 kv x 64 dh. FIXED: strictly bounded linear index decomposition.
// ==================================================================
__global__ void __launch_bounds__(256)
vt_kernel(const __half* __restrict__ V, __half* __restrict__ VT)
{
    __shared__ __half sm[32][65];
    const int bh = blockIdx.y;
    const int b = bh >> 4;
    const int h = bh & 15;
    const int kv0 = blockIdx.x * 32;
    const int tid = threadIdx.x;

    // load: 32 kv x 32 dh-pairs = 1024 half2
#pragma unroll
    for (int i = 0; i < 4; i++) {
        int idx = tid + i * 256;          // 0..1023
        int kv = idx >> 5;                // 0..31
        int dp = idx & 31;                // dh pair 0..31
        __half2 v = *(const __half2*)&V[(size_t)(b * Nc + kv0 + kv) * Dc + h * DHc + dp * 2];
        sm[kv][dp * 2]     = __low2half(v);
        sm[kv][dp * 2 + 1] = __high2half(v);
    }
    __syncthreads();

    // store: 64 dh x 16 kv-pairs = 1024 half2
#pragma unroll
    for (int i = 0; i < 4; i++) {
        int idx = tid + i * 256;          // 0..1023
        int dh = idx >> 4;                // 0..63
        int kp = idx & 15;                // kv pair 0..15
        __half2 o = __halves2half2(sm[kp * 2][dh], sm[kp * 2 + 1][dh]);
        *(__half2*)&VT[(size_t)bh * DHc * Nc + (size_t)dh * Nc + kv0 + kp * 2] = o;
    }
}

// ==================================================================
// Softmax over 512 fp32 scores -> fp16 probs
// ==================================================================
__global__ void __launch_bounds__(256)
softmax512_kernel(const float* __restrict__ S, __half* __restrict__ P)
{
    const size_t row = blockIdx.x;
    const float* p = S + row * Nc;
    __half* po = P + row * Nc;
    const int tid = threadIdx.x;

    float v0 = p[tid];
    float v1 = p[tid + 256];

    __shared__ float red[8];
    float m = fmaxf(v0, v1);
    for (int o = 16; o > 0; o >>= 1) m = fmaxf(m, __shfl_down_sync(0xffffffffu, m, o));
    if ((tid & 31) == 0) red[tid >> 5] = m;
    __syncthreads();
    if (tid < 32) {
        m = (tid < 8) ? red[tid] : -INFINITY;
        for (int o = 4; o > 0; o >>= 1) m = fmaxf(m, __shfl_down_sync(0xffffffffu, m, o));
        if (tid == 0) red[0] = m;
    }
    __syncthreads();
    m = red[0];
    __syncthreads();

    float e0 = expf(v0 - m);
    float e1 = expf(v1 - m);
    float s = e0 + e1;
    for (int o = 16; o > 0; o >>= 1) s += __shfl_down_sync(0xffffffffu, s, o);
    if ((tid & 31) == 0) red[tid >> 5] = s;
    __syncthreads();
    if (tid < 32) {
        s = (tid < 8) ? red[tid] : 0.f;
        for (int o = 4; o > 0; o >>= 1) s += __shfl_down_sync(0xffffffffu, s, o);
        if (tid == 0) red[0] = s;
    }
    __syncthreads();
    s = red[0];

    float inv = 1.f / s;
    po[tid] = __float2half(e0 * inv);
    po[tid + 256] = __float2half(e1 * inv);
}

// ==================================================================
// Residual + LayerNorm -> fp32 x AND fp16 x16
// ==================================================================
__global__ void __launch_bounds__(256)
add_ln_kernel(const float* __restrict__ A, const float* __restrict__ X,
              const float* __restrict__ gamma, const float* __restrict__ beta,
              float* __restrict__ out, __half* __restrict__ out16)
{
    const size_t row = blockIdx.x;
    const int tid = threadIdx.x;
    float vals[4];
    float s = 0.f, ss = 0.f;
#pragma unroll
    for (int i = 0; i < 4; i++) {
        int c = tid + i * 256;
        float v = A[row * Dc + c] + X[row * Dc + c];
        vals[i] = v;
        s += v;
        ss += v * v;
    }
    __shared__ float sa[8], sb_[8];
    int lane = tid & 31, w = tid >> 5;
    for (int o = 16; o > 0; o >>= 1) {
        s  += __shfl_down_sync(0xffffffffu, s, o);
        ss += __shfl_down_sync(0xffffffffu, ss, o);
    }
    if (lane == 0) { sa[w] = s; sb_[w] = ss; }
    __syncthreads();
    if (w == 0) {
        s  = (lane < 8) ? sa[lane] : 0.f;
        ss = (lane < 8) ? sb_[lane] : 0.f;
        for (int o = 4; o > 0; o >>= 1) {
            s  += __shfl_down_sync(0xffffffffu, s, o);
            ss += __shfl_down_sync(0xffffffffu, ss, o);
        }
        if (lane == 0) { sa[0] = s; sb_[0] = ss; }
    }
    __syncthreads();
    float mean = sa[0] * (1.f / Dc);
    float var = sb_[0] * (1.f / Dc) - mean * mean;
    float inv = rsqrtf(var + EPSc);
#pragma unroll
    for (int i = 0; i < 4; i++) {
        int c = tid + i * 256;
        float o = gamma[c] * (vals[i] - mean) * inv + beta[c];
        out[row * Dc + c] = o;
        out16[row * Dc + c] = __float2half(o);
    }
}

// ==================================================================
// Batched weight transpose+convert: W[z][K,N] fp32 -> T[z][N,K] fp16
// ==================================================================
__global__ void __launch_bounds__(256)
wt_kernel(const float* __restrict__ Wbase, __half* __restrict__ Tbase, int K, int N)
{
    __shared__ float t[32][33];
    const float* W = Wbase + (size_t)blockIdx.z * K * N;
    __half* T = Tbase + (size_t)blockIdx.z * K * N;
    const int n0 = blockIdx.x * 32;
    const int k0 = blockIdx.y * 32;
    const int tx = threadIdx.x & 31;
    const int ty = threadIdx.x >> 5;
#pragma unroll
    for (int i = 0; i < 4; i++)
        t[ty + i * 8][tx] = W[(size_t)(k0 + ty + i * 8) * N + n0 + tx];
    __syncthreads();
#pragma unroll
    for (int i = 0; i < 4; i++)
        T[(size_t)(n0 + ty + i * 8) * K + k0 + tx] = __float2half(t[tx][ty + i * 8]);
}

// ------------------------------------------------------------------
// misc
// ------------------------------------------------------------------
__global__ void copy4_kernel(float4* __restrict__ dst, const float4* __restrict__ src, int n4) {
    int i = blockIdx.x * blockDim.x + threadIdx.x;
    if (i < n4) dst[i] = src[i];
}
__global__ void __launch_bounds__(256)
f2h_kernel(const float* __restrict__ in, __half* __restrict__ out, int n)
{
    int i = (blockIdx.x * 256 + threadIdx.x) * 4;
    if (i >= n) return;
    float4 v = *(const float4*)(in + i);
    *(__half2*)(out + i)     = __floats2half2_rn(v.x, v.y);
    *(__half2*)(out + i + 2) = __floats2half2_rn(v.z, v.w);
}

// ------------------------------------------------------------------
// Host orchestration
// ------------------------------------------------------------------
extern "C" void kernel_launch(void* const* d_in, const int* in_sizes, int n_in,
                              void* d_out, int out_size)
{
    const float* trg  = (const float*)d_in[0];
    const float* enc  = (const float*)d_in[1];
    const int*   mask = (const int*)  d_in[2];
    const float* sa_w = (const float*)d_in[3];
    const float* sa_b = (const float*)d_in[4];
    const float* ca_w = (const float*)d_in[5];
    const float* ca_b = (const float*)d_in[6];
    const float* ln_g = (const float*)d_in[7];
    const float* ln_b = (const float*)d_in[8];
    const float* w1   = (const float*)d_in[9];
    const float* b1   = (const float*)d_in[10];
    const float* w2   = (const float*)d_in[11];
    const float* b2   = (const float*)d_in[12];
    float* out = (float*)d_out;

    float *x, *t, *s;
    __half *x16, *e16, *q16, *k16, *v16, *vt16, *ao16, *ff16, *p16;
    __half *wsa, *wca, *w1t, *w2t;
    cudaGetSymbolAddress((void**)&x,  g_x);
    cudaGetSymbolAddress((void**)&t,  g_t);
    cudaGetSymbolAddress((void**)&s,  g_s);
    cudaGetSymbolAddress((void**)&x16, g_x16);
    cudaGetSymbolAddress((void**)&e16, g_e16);
    cudaGetSymbolAddress((void**)&q16, g_q16);
    cudaGetSymbolAddress((void**)&k16, g_k16);
    cudaGetSymbolAddress((void**)&v16, g_v16);
    cudaGetSymbolAddress((void**)&vt16, g_vt16);
    cudaGetSymbolAddress((void**)&ao16, g_ao16);
    cudaGetSymbolAddress((void**)&ff16, g_ff16);
    cudaGetSymbolAddress((void**)&p16, g_p16);
    cudaGetSymbolAddress((void**)&wsa, g_wsa);
    cudaGetSymbolAddress((void**)&wca, g_wca);
    cudaGetSymbolAddress((void**)&w1t, g_w1t);
    cudaGetSymbolAddress((void**)&w2t, g_w2t);

    cudaFuncSetAttribute(gemm_mma_kernel<false,false>, cudaFuncAttributeMaxDynamicSharedMemorySize, GEMM_SMEM);
    cudaFuncSetAttribute(gemm_mma_kernel<false,true>,  cudaFuncAttributeMaxDynamicSharedMemorySize, GEMM_SMEM);
    cudaFuncSetAttribute(gemm_mma_kernel<true,true>,   cudaFuncAttributeMaxDynamicSharedMemorySize, GEMM_SMEM);
    cudaFuncSetAttribute(scores_mma_kernel, cudaFuncAttributeMaxDynamicSharedMemorySize, SCORE_SMEM);
    cudaFuncSetAttribute(pv_mma_kernel,     cudaFuncAttributeMaxDynamicSharedMemorySize, PV_SMEM);

    const int nElem = Mrows * Dc;
    copy4_kernel<<<(nElem / 4 + 255) / 256, 256>>>((float4*)x, (const float4*)trg, nElem / 4);
    f2h_kernel<<<(nElem / 4 + 255) / 256, 256>>>(trg, x16, nElem);
    f2h_kernel<<<(nElem / 4 + 255) / 256, 256>>>(enc, e16, nElem);

    // upfront weight transposes (batched)
    wt_kernel<<<dim3(32, 32, 24), 256>>>(sa_w, wsa, Dc, Dc);
    wt_kernel<<<dim3(32, 32, 24), 256>>>(ca_w, wca, Dc, Dc);
    wt_kernel<<<dim3(128, 32, 6), 256>>>(w1, w1t, Dc, FFc);
    wt_kernel<<<dim3(32, 128, 6), 256>>>(w2, w2t, FFc, Dc);

    dim3 gProj(Dc / 128, Mrows / 128);       // (8, 32)
    dim3 gFF1(FFc / 128, Mrows / 128);       // (32, 32)
    dim3 gScore(4, 4, Bc * Hc);
    dim3 gPV(4, Bc * Hc);
    dim3 gVT(16, Bc * Hc);
    const int nRowsS = Bc * Hc * Nc;

    for (int l = 0; l < Lc; l++) {
        const __half* Ws = wsa + (size_t)l * 4 * Dc * Dc;
        const __half* Wc = wca + (size_t)l * 4 * Dc * Dc;
        const float* Bs = sa_b + (size_t)l * 4 * Dc;
        const float* Bcp = ca_b + (size_t)l * 4 * Dc;

        // ===== self-attention =====
        gemm_mma_kernel<false,true><<<gProj, 256, GEMM_SMEM>>>(x16, Ws + 0 * Dc * Dc, Bs + 0 * Dc, q16, Mrows, Dc, Dc);
        gemm_mma_kernel<false,true><<<gProj, 256, GEMM_SMEM>>>(x16, Ws + 1 * Dc * Dc, Bs + 1 * Dc, k16, Mrows, Dc, Dc);
        gemm_mma_kernel<false,true><<<gProj, 256, GEMM_SMEM>>>(x16, Ws + 2 * Dc * Dc, Bs + 2 * Dc, v16, Mrows, Dc, Dc);
        vt_kernel<<<gVT, 256>>>(v16, vt16);
        scores_mma_kernel<<<gScore, 256, SCORE_SMEM>>>(q16, k16, mask, s, 1);
        softmax512_kernel<<<nRowsS, 256>>>(s, p16);
        pv_mma_kernel<<<gPV, 256, PV_SMEM>>>(p16, vt16, ao16);
        gemm_mma_kernel<false,false><<<gProj, 256, GEMM_SMEM>>>(ao16, Ws + 3 * Dc * Dc, Bs + 3 * Dc, t, Mrows, Dc, Dc);
        add_ln_kernel<<<Mrows, 256>>>(t, x, ln_g + ((size_t)l * 3 + 0) * Dc, ln_b + ((size_t)l * 3 + 0) * Dc, x, x16);

        // ===== cross-attention =====
        gemm_mma_kernel<false,true><<<gProj, 256, GEMM_SMEM>>>(x16, Wc + 0 * Dc * Dc, Bcp + 0 * Dc, q16, Mrows, Dc, Dc);
        gemm_mma_kernel<false,true><<<gProj, 256, GEMM_SMEM>>>(e16, Wc + 1 * Dc * Dc, Bcp + 1 * Dc, k16, Mrows, Dc, Dc);
        gemm_mma_kernel<false,true><<<gProj, 256, GEMM_SMEM>>>(e16, Wc + 2 * Dc * Dc, Bcp + 2 * Dc, v16, Mrows, Dc, Dc);
        vt_kernel<<<gVT, 256>>>(v16, vt16);
        scores_mma_kernel<<<gScore, 256, SCORE_SMEM>>>(q16, k16, mask, s, 0);
        softmax512_kernel<<<nRowsS, 256>>>(s, p16);
        pv_mma_kernel<<<gPV, 256, PV_SMEM>>>(p16, vt16, ao16);
        gemm_mma_kernel<false,false><<<gProj, 256, GEMM_SMEM>>>(ao16, Wc + 3 * Dc * Dc, Bcp + 3 * Dc, t, Mrows, Dc, Dc);
        add_ln_kernel<<<Mrows, 256>>>(t, x, ln_g + ((size_t)l * 3 + 1) * Dc, ln_b + ((size_t)l * 3 + 1) * Dc, x, x16);

        // ===== FFN =====
        gemm_mma_kernel<true,true><<<gFF1, 256, GEMM_SMEM>>>(x16, w1t + (size_t)l * Dc * FFc, b1 + (size_t)l * FFc, ff16, Mrows, FFc, Dc);
        gemm_mma_kernel<false,false><<<gProj, 256, GEMM_SMEM>>>(ff16, w2t + (size_t)l * FFc * Dc, b2 + (size_t)l * Dc, t, Mrows, Dc, FFc);
        add_ln_kernel<<<Mrows, 256>>>(t, x, ln_g + ((size_t)l * 3 + 2) * Dc, ln_b + ((size_t)l * 3 + 2) * Dc, x, x16);
    }

    copy4_kernel<<<(nElem / 4 + 255) / 256, 256>>>((float4*)out, (const float4*)x, nElem / 4);
}

// round 6
// speedup vs baseline: 6.5654x; 1.2768x over previous
#include <cuda_runtime.h>
#include <cuda_fp16.h>
#include <math.h>
#include <stdint.h>

// Problem constants
#define Lc   6
#define Dc   1024
#define Hc   16
#define DHc  64
#define FFc  4096
#define Bc   8
#define Nc   512
#define Mrows (Bc*Nc)          // 4096
#define EPSc 1e-12f

// ------------------------------------------------------------------
// Scratch (device globals)
// ------------------------------------------------------------------
__device__ float g_x [Mrows*Dc];
__device__ float g_t [Mrows*Dc];

__device__ __half g_x16[Mrows*Dc];
__device__ __half g_e16[Mrows*Dc];
__device__ __half g_qkv16[(size_t)Mrows*3*Dc];  // fused QKV (self) [4096][3072]
__device__ __half g_q16[Mrows*Dc];              // cross Q
__device__ __half g_kv16[(size_t)Mrows*2*Dc];   // cross KV [4096][2048]
__device__ __half g_vt16[Mrows*Dc];             // [bh][dh=64][kv=512]
__device__ __half g_ao16[Mrows*Dc];
__device__ __half g_ff16[(size_t)Mrows*FFc];
__device__ __half g_bias16[(size_t)Bc*Nc*Nc];   // mask additive bias fp16

// transposed fp16 weights (built once per launch)
__device__ __half g_wsa[(size_t)Lc*4*Dc*Dc];
__device__ __half g_wca[(size_t)Lc*4*Dc*Dc];
__device__ __half g_w1t[(size_t)Lc*Dc*FFc];
__device__ __half g_w2t[(size_t)Lc*FFc*Dc];

// ------------------------------------------------------------------
// PTX helpers
// ------------------------------------------------------------------
__device__ __forceinline__ uint32_t smem_u32(const void* p) {
    uint32_t a;
    asm("{ .reg .u64 t; cvta.to.shared.u64 t, %1; cvt.u32.u64 %0, t; }" : "=r"(a) : "l"(p));
    return a;
}
__device__ __forceinline__ void cp16(uint32_t dst, const void* src) {
    asm volatile("cp.async.cg.shared.global [%0], [%1], 16;" :: "r"(dst), "l"(src) : "memory");
}
#define CP_COMMIT() asm volatile("cp.async.commit_group;" ::: "memory")

__device__ __forceinline__ void ldsm4(uint32_t& r0, uint32_t& r1, uint32_t& r2, uint32_t& r3, uint32_t addr) {
    asm volatile("ldmatrix.sync.aligned.m8n8.x4.shared.b16 {%0,%1,%2,%3}, [%4];"
        : "=r"(r0), "=r"(r1), "=r"(r2), "=r"(r3) : "r"(addr));
}
__device__ __forceinline__ void mma16816(float* c, const uint32_t* a, uint32_t b0, uint32_t b1) {
    asm volatile(
        "mma.sync.aligned.m16n8k16.row.col.f32.f16.f16.f32 "
        "{%0,%1,%2,%3}, {%4,%5,%6,%7}, {%8,%9}, {%0,%1,%2,%3};"
        : "+f"(c[0]), "+f"(c[1]), "+f"(c[2]), "+f"(c[3])
        : "r"(a[0]), "r"(a[1]), "r"(a[2]), "r"(a[3]), "r"(b0), "r"(b1));
}
__device__ __forceinline__ uint32_t packh2(float a, float b) {
    __half2 h = __floats2half2_rn(a, b);
    return *(uint32_t*)&h;
}

// ==================================================================
// Dense GEMM: C[M,N] = A[M,K] @ Bt[N,K]^T + bias (+ReLU). fp16/fp32 out.
// BM=128, BN=128, BK=32, 4-stage cp.async, 256 threads.
// ==================================================================
#define GEMM_SMEM (4 * 20480)

__device__ __forceinline__ void cp_stage_g(uint32_t sbase,
    const __half* __restrict__ A, const __half* __restrict__ B,
    int m0, int n0, int k0, int K, int tid)
{
#pragma unroll
    for (int j = 0; j < 2; j++) {
        int id = tid + 256 * j;
        int row = id >> 2;
        int c = id & 3;
        uint32_t d = (uint32_t)(row * 80 + c * 16);
        cp16(sbase + d,         A + (size_t)(m0 + row) * K + k0 + c * 8);
        cp16(sbase + 10240 + d, B + (size_t)(n0 + row) * K + k0 + c * 8);
    }
}

template<bool RELU, bool HOUT>
__global__ void __launch_bounds__(256, 2)
gemm_mma_kernel(const __half* __restrict__ A, const __half* __restrict__ B,
                const float* __restrict__ bias, void* __restrict__ Cout,
                int M, int N, int K)
{
    extern __shared__ char sm_[];
    const uint32_t sb = smem_u32(sm_);
    const int tid = threadIdx.x;
    const int wid = tid >> 5;
    const int l = tid & 31;
    const int m0 = blockIdx.y * 128;
    const int n0 = blockIdx.x * 128;
    const int wm = (wid >> 1) * 32;
    const int wn = (wid & 1) * 64;
    const int KT = K >> 5;

    float c[2][8][4];
#pragma unroll
    for (int i = 0; i < 2; i++)
#pragma unroll
        for (int j = 0; j < 8; j++)
#pragma unroll
            for (int r = 0; r < 4; r++) c[i][j][r] = 0.f;

#pragma unroll
    for (int s = 0; s < 3; s++) {
        cp_stage_g(sb + s * 20480, A, B, m0, n0, s * 32, K, tid);
        CP_COMMIT();
    }

    const uint32_t aoff = (uint32_t)((wm + (l & 15)) * 80 + (l >> 4) * 16);
    const uint32_t boff = (uint32_t)((wn + (l & 7) + ((l >> 3) & 1) * 8) * 80 + (l >> 4) * 16);

    for (int kt = 0; kt < KT; kt++) {
        asm volatile("cp.async.wait_group 2;" ::: "memory");
        __syncthreads();

        const int pf = kt + 3;
        if (pf < KT) cp_stage_g(sb + (pf & 3) * 20480, A, B, m0, n0, pf * 32, K, tid);
        CP_COMMIT();

        const uint32_t sA = sb + (kt & 3) * 20480;
        const uint32_t sB = sA + 10240;

#pragma unroll
        for (int kk = 0; kk < 2; kk++) {
            uint32_t a[2][4], b[4][4];
            ldsm4(a[0][0], a[0][1], a[0][2], a[0][3], sA + aoff + kk * 32);
            ldsm4(a[1][0], a[1][1], a[1][2], a[1][3], sA + aoff + 16 * 80 + kk * 32);
#pragma unroll
            for (int j = 0; j < 4; j++)
                ldsm4(b[j][0], b[j][1], b[j][2], b[j][3], sB + boff + j * 16 * 80 + kk * 32);
#pragma unroll
            for (int mi = 0; mi < 2; mi++)
#pragma unroll
                for (int nj = 0; nj < 8; nj++)
                    mma16816(c[mi][nj], a[mi], b[nj >> 1][nj & 1], b[nj >> 1][(nj & 1) + 2]);
        }
    }

    const int row0 = m0 + wm + (l >> 2);
    const int colb = n0 + wn + (l & 3) * 2;
#pragma unroll
    for (int mi = 0; mi < 2; mi++) {
#pragma unroll
        for (int nj = 0; nj < 8; nj++) {
            const int col = colb + nj * 8;
            const float b0 = bias[col], b1 = bias[col + 1];
            float v0 = c[mi][nj][0] + b0;
            float v1 = c[mi][nj][1] + b1;
            float v2 = c[mi][nj][2] + b0;
            float v3 = c[mi][nj][3] + b1;
            if (RELU) {
                v0 = fmaxf(v0, 0.f); v1 = fmaxf(v1, 0.f);
                v2 = fmaxf(v2, 0.f); v3 = fmaxf(v3, 0.f);
            }
            const int r0 = row0 + mi * 16;
            if (HOUT) {
                __half* C = (__half*)Cout;
                *(__half2*)&C[(size_t)r0 * N + col]       = __floats2half2_rn(v0, v1);
                *(__half2*)&C[(size_t)(r0 + 8) * N + col] = __floats2half2_rn(v2, v3);
            } else {
                float* C = (float*)Cout;
                float2 p0; p0.x = v0; p0.y = v1;
                float2 p1; p1.x = v2; p1.y = v3;
                *(float2*)&C[(size_t)r0 * N + col] = p0;
                *(float2*)&C[(size_t)(r0 + 8) * N + col] = p1;
            }
        }
    }
}

// ==================================================================
// Flash attention: O = softmax(Q K^T / 8 + bias) V
// Q rows: BM=128 per CTA (8 warps x 16 rows). kv chunks of 64, 8 chunks.
// Q/K read head-strided from projection buffers; V^T from vt16.
// smem: Q 128x144B | 2 x (K 64x144B + VT 64x144B) = 55296 B
// ==================================================================
#define FL_SMEM (18432 + 2 * 18432)

__global__ void __launch_bounds__(256, 2)
flash_kernel(const __half* __restrict__ Qg, int qStride,
             const __half* __restrict__ Kg, int kStride,
             const __half* __restrict__ VTg,
             const __half* __restrict__ biasMask,   // [b][q][k] or nullptr
             __half* __restrict__ O)
{
    extern __shared__ char sm_[];
    const uint32_t sb = smem_u32(sm_);
    const int tid = threadIdx.x;
    const int wid = tid >> 5;
    const int l = tid & 31;
    const int bh = blockIdx.y;
    const int b = bh >> 4;
    const int h = bh & 15;
    const int q0 = blockIdx.x * 128;
    const int wm = wid * 16;

    const __half* Qb = Qg + h * DHc;
    const __half* Kb = Kg + h * DHc;
    const __half* VTb = VTg + (size_t)bh * DHc * Nc;

    const uint32_t sQ = sb;
    // buffers: K at sb+18432+buf*18432, VT at +9216

    // ---- load Q tile (128 x 64) + chunk 0 ----
#pragma unroll
    for (int j = 0; j < 4; j++) {
        int idx = tid + 256 * j;          // 0..1023
        int row = idx >> 3;
        int c = idx & 7;
        cp16(sQ + (uint32_t)(row * 144 + c * 16),
             Qb + (size_t)(b * Nc + q0 + row) * qStride + c * 8);
    }
    {
        uint32_t sK = sb + 18432;
        uint32_t sV = sK + 9216;
#pragma unroll
        for (int j = 0; j < 2; j++) {
            int idx = tid + 256 * j;      // 0..511
            int row = idx >> 3;           // 0..63
            int c = idx & 7;
            cp16(sK + (uint32_t)(row * 144 + c * 16),
                 Kb + (size_t)(b * Nc + row) * kStride + c * 8);
            cp16(sV + (uint32_t)(row * 144 + c * 16),
                 VTb + (size_t)row * Nc + c * 8);
        }
    }
    CP_COMMIT();

    float o[8][4];
#pragma unroll
    for (int j = 0; j < 8; j++)
#pragma unroll
        for (int r = 0; r < 4; r++) o[j][r] = 0.f;
    float mrow[2] = { -INFINITY, -INFINITY };
    float lsum[2] = { 0.f, 0.f };

    const uint32_t aoff = (uint32_t)((wm + (l & 15)) * 144 + (l >> 4) * 16);
    const uint32_t boff = (uint32_t)(((l & 7) + ((l >> 3) & 1) * 8) * 144 + (l >> 4) * 16);
    const int r0g = q0 + wm + (l >> 2);   // global q row (first of pair)

    for (int t = 0; t < 8; t++) {
        // prefetch next chunk into other buffer
        if (t < 7) {
            uint32_t sK = sb + 18432 + ((t + 1) & 1) * 18432;
            uint32_t sV = sK + 9216;
            const int kv0 = (t + 1) * 64;
#pragma unroll
            for (int j = 0; j < 2; j++) {
                int idx = tid + 256 * j;
                int row = idx >> 3;
                int c = idx & 7;
                cp16(sK + (uint32_t)(row * 144 + c * 16),
                     Kb + (size_t)(b * Nc + kv0 + row) * kStride + c * 8);
                cp16(sV + (uint32_t)(row * 144 + c * 16),
                     VTb + (size_t)row * Nc + kv0 + c * 8);
            }
            CP_COMMIT();
            asm volatile("cp.async.wait_group 1;" ::: "memory");
        } else {
            asm volatile("cp.async.wait_group 0;" ::: "memory");
        }
        __syncthreads();

        const uint32_t sK = sb + 18432 + (t & 1) * 18432;
        const uint32_t sV = sK + 9216;

        // ---- S = Q K^T over d=64 (4 k16 chunks) ----
        float s[8][4];
#pragma unroll
        for (int j = 0; j < 8; j++)
#pragma unroll
            for (int r = 0; r < 4; r++) s[j][r] = 0.f;

#pragma unroll
        for (int kk = 0; kk < 4; kk++) {
            uint32_t a[4], bf[4][4];
            ldsm4(a[0], a[1], a[2], a[3], sQ + aoff + kk * 32);
#pragma unroll
            for (int j = 0; j < 4; j++)
                ldsm4(bf[j][0], bf[j][1], bf[j][2], bf[j][3], sK + boff + j * 16 * 144 + kk * 32);
#pragma unroll
            for (int j = 0; j < 4; j++) {
                mma16816(s[2 * j],     a, bf[j][0], bf[j][2]);
                mma16816(s[2 * j + 1], a, bf[j][1], bf[j][3]);
            }
        }

        // ---- scale + additive mask bias ----
        const int colb = t * 64 + (l & 3) * 2;
        if (biasMask != nullptr) {
#pragma unroll
            for (int nj = 0; nj < 8; nj++) {
                const int col = colb + nj * 8;
                __half2 b0 = *(const __half2*)&biasMask[((size_t)b * Nc + r0g) * Nc + col];
                __half2 b1 = *(const __half2*)&biasMask[((size_t)b * Nc + r0g + 8) * Nc + col];
                s[nj][0] = s[nj][0] * 0.125f + __low2float(b0);
                s[nj][1] = s[nj][1] * 0.125f + __high2float(b0);
                s[nj][2] = s[nj][2] * 0.125f + __low2float(b1);
                s[nj][3] = s[nj][3] * 0.125f + __high2float(b1);
            }
        } else {
#pragma unroll
            for (int nj = 0; nj < 8; nj++) {
                s[nj][0] *= 0.125f; s[nj][1] *= 0.125f;
                s[nj][2] *= 0.125f; s[nj][3] *= 0.125f;
            }
        }

        // ---- online softmax ----
        float m0 = -INFINITY, m1 = -INFINITY;
#pragma unroll
        for (int nj = 0; nj < 8; nj++) {
            m0 = fmaxf(m0, fmaxf(s[nj][0], s[nj][1]));
            m1 = fmaxf(m1, fmaxf(s[nj][2], s[nj][3]));
        }
        m0 = fmaxf(m0, __shfl_xor_sync(0xffffffffu, m0, 1));
        m0 = fmaxf(m0, __shfl_xor_sync(0xffffffffu, m0, 2));
        m1 = fmaxf(m1, __shfl_xor_sync(0xffffffffu, m1, 1));
        m1 = fmaxf(m1, __shfl_xor_sync(0xffffffffu, m1, 2));

        const float mn0 = fmaxf(mrow[0], m0);
        const float mn1 = fmaxf(mrow[1], m1);
        const float sc0 = expf(mrow[0] - mn0);
        const float sc1 = expf(mrow[1] - mn1);
        mrow[0] = mn0; mrow[1] = mn1;

        float rs0 = 0.f, rs1 = 0.f;
#pragma unroll
        for (int nj = 0; nj < 8; nj++) {
            s[nj][0] = expf(s[nj][0] - mn0);
            s[nj][1] = expf(s[nj][1] - mn0);
            s[nj][2] = expf(s[nj][2] - mn1);
            s[nj][3] = expf(s[nj][3] - mn1);
            rs0 += s[nj][0] + s[nj][1];
            rs1 += s[nj][2] + s[nj][3];
        }
        rs0 += __shfl_xor_sync(0xffffffffu, rs0, 1);
        rs0 += __shfl_xor_sync(0xffffffffu, rs0, 2);
        rs1 += __shfl_xor_sync(0xffffffffu, rs1, 1);
        rs1 += __shfl_xor_sync(0xffffffffu, rs1, 2);
        lsum[0] = lsum[0] * sc0 + rs0;
        lsum[1] = lsum[1] * sc1 + rs1;

#pragma unroll
        for (int j = 0; j < 8; j++) {
            o[j][0] *= sc0; o[j][1] *= sc0;
            o[j][2] *= sc1; o[j][3] *= sc1;
        }

        // ---- O += P @ V (k=64, 4 k16 chunks; A from s-frags) ----
#pragma unroll
        for (int kk = 0; kk < 4; kk++) {
            uint32_t a[4];
            a[0] = packh2(s[2 * kk][0],     s[2 * kk][1]);
            a[1] = packh2(s[2 * kk][2],     s[2 * kk][3]);
            a[2] = packh2(s[2 * kk + 1][0], s[2 * kk + 1][1]);
            a[3] = packh2(s[2 * kk + 1][2], s[2 * kk + 1][3]);
            uint32_t bf[4][4];
#pragma unroll
            for (int j = 0; j < 4; j++)
                ldsm4(bf[j][0], bf[j][1], bf[j][2], bf[j][3], sV + boff + j * 16 * 144 + kk * 32);
#pragma unroll
            for (int j = 0; j < 4; j++) {
                mma16816(o[2 * j],     a, bf[j][0], bf[j][2]);
                mma16816(o[2 * j + 1], a, bf[j][1], bf[j][3]);
            }
        }
        __syncthreads();
    }

    // ---- epilogue ----
    const float inv0 = 1.f / lsum[0];
    const float inv1 = 1.f / lsum[1];
#pragma unroll
    for (int njo = 0; njo < 8; njo++) {
        const int gc = h * DHc + njo * 8 + (l & 3) * 2;
        *(__half2*)&O[(size_t)(b * Nc + r0g) * Dc + gc] =
            __floats2half2_rn(o[njo][0] * inv0, o[njo][1] * inv0);
        *(__half2*)&O[(size_t)(b * Nc + r0g + 8) * Dc + gc] =
            __floats2half2_rn(o[njo][2] * inv1, o[njo][3] * inv1);
    }
}

// ==================================================================
// V transpose: V (head-strided rows) -> vt16[bh][dh][kv]
// ==================================================================
__global__ void __launch_bounds__(256)
vt_kernel(const __half* __restrict__ V, int vStride, __half* __restrict__ VT)
{
    __shared__ __half sm[32][65];
    const int bh = blockIdx.y;
    const int b = bh >> 4;
    const int h = bh & 15;
    const int kv0 = blockIdx.x * 32;
    const int tid = threadIdx.x;

#pragma unroll
    for (int i = 0; i < 4; i++) {
        int idx = tid + i * 256;
        int kv = idx >> 5;
        int dp = idx & 31;
        __half2 v = *(const __half2*)&V[(size_t)(b * Nc + kv0 + kv) * vStride + h * DHc + dp * 2];
        sm[kv][dp * 2]     = __low2half(v);
        sm[kv][dp * 2 + 1] = __high2half(v);
    }
    __syncthreads();
#pragma unroll
    for (int i = 0; i < 4; i++) {
        int idx = tid + i * 256;
        int dh = idx >> 4;
        int kp = idx & 15;
        __half2 o = __halves2half2(sm[kp * 2][dh], sm[kp * 2 + 1][dh]);
        *(__half2*)&VT[(size_t)bh * DHc * Nc + (size_t)dh * Nc + kv0 + kp * 2] = o;
    }
}

// ==================================================================
// Mask -> fp16 additive bias (0 / -10000), once per launch
// ==================================================================
__global__ void __launch_bounds__(256)
maskbias_kernel(const int* __restrict__ mask, __half* __restrict__ bias, int n)
{
    int i = (blockIdx.x * 256 + threadIdx.x) * 4;
    if (i >= n) return;
    int4 m = *(const int4*)(mask + i);
    __half z = __float2half(0.f), neg = __float2half(-10000.f);
    bias[i]     = m.x ? z : neg;
    bias[i + 1] = m.y ? z : neg;
    bias[i + 2] = m.z ? z : neg;
    bias[i + 3] = m.w ? z : neg;
}

// ==================================================================
// Residual + LayerNorm -> fp32 x AND fp16 x16
// ==================================================================
__global__ void __launch_bounds__(256)
add_ln_kernel(const float* __restrict__ A, const float* __restrict__ X,
              const float* __restrict__ gamma, const float* __restrict__ beta,
              float* __restrict__ out, __half* __restrict__ out16)
{
    const size_t row = blockIdx.x;
    const int tid = threadIdx.x;
    float vals[4];
    float s = 0.f, ss = 0.f;
#pragma unroll
    for (int i = 0; i < 4; i++) {
        int c = tid + i * 256;
        float v = A[row * Dc + c] + X[row * Dc + c];
        vals[i] = v;
        s += v;
        ss += v * v;
    }
    __shared__ float sa[8], sb_[8];
    int lane = tid & 31, w = tid >> 5;
    for (int o = 16; o > 0; o >>= 1) {
        s  += __shfl_down_sync(0xffffffffu, s, o);
        ss += __shfl_down_sync(0xffffffffu, ss, o);
    }
    if (lane == 0) { sa[w] = s; sb_[w] = ss; }
    __syncthreads();
    if (w == 0) {
        s  = (lane < 8) ? sa[lane] : 0.f;
        ss = (lane < 8) ? sb_[lane] : 0.f;
        for (int o = 4; o > 0; o >>= 1) {
            s  += __shfl_down_sync(0xffffffffu, s, o);
            ss += __shfl_down_sync(0xffffffffu, ss, o);
        }
        if (lane == 0) { sa[0] = s; sb_[0] = ss; }
    }
    __syncthreads();
    float mean = sa[0] * (1.f / Dc);
    float var = sb_[0] * (1.f / Dc) - mean * mean;
    float inv = rsqrtf(var + EPSc);
#pragma unroll
    for (int i = 0; i < 4; i++) {
        int c = tid + i * 256;
        float o = gamma[c] * (vals[i] - mean) * inv + beta[c];
        out[row * Dc + c] = o;
        out16[row * Dc + c] = __float2half(o);
    }
}

// ==================================================================
// Batched weight transpose+convert: W[z][K,N] fp32 -> T[z][N,K] fp16
// ==================================================================
__global__ void __launch_bounds__(256)
wt_kernel(const float* __restrict__ Wbase, __half* __restrict__ Tbase, int K, int N)
{
    __shared__ float t[32][33];
    const float* W = Wbase + (size_t)blockIdx.z * K * N;
    __half* T = Tbase + (size_t)blockIdx.z * K * N;
    const int n0 = blockIdx.x * 32;
    const int k0 = blockIdx.y * 32;
    const int tx = threadIdx.x & 31;
    const int ty = threadIdx.x >> 5;
#pragma unroll
    for (int i = 0; i < 4; i++)
        t[ty + i * 8][tx] = W[(size_t)(k0 + ty + i * 8) * N + n0 + tx];
    __syncthreads();
#pragma unroll
    for (int i = 0; i < 4; i++)
        T[(size_t)(n0 + ty + i * 8) * K + k0 + tx] = __float2half(t[tx][ty + i * 8]);
}

// ------------------------------------------------------------------
// misc
// ------------------------------------------------------------------
__global__ void copy4_kernel(float4* __restrict__ dst, const float4* __restrict__ src, int n4) {
    int i = blockIdx.x * blockDim.x + threadIdx.x;
    if (i < n4) dst[i] = src[i];
}
__global__ void __launch_bounds__(256)
f2h_kernel(const float* __restrict__ in, __half* __restrict__ out, int n)
{
    int i = (blockIdx.x * 256 + threadIdx.x) * 4;
    if (i >= n) return;
    float4 v = *(const float4*)(in + i);
    *(__half2*)(out + i)     = __floats2half2_rn(v.x, v.y);
    *(__half2*)(out + i + 2) = __floats2half2_rn(v.z, v.w);
}

// ------------------------------------------------------------------
// Host orchestration
// ------------------------------------------------------------------
extern "C" void kernel_launch(void* const* d_in, const int* in_sizes, int n_in,
                              void* d_out, int out_size)
{
    const float* trg  = (const float*)d_in[0];
    const float* enc  = (const float*)d_in[1];
    const int*   mask = (const int*)  d_in[2];
    const float* sa_w = (const float*)d_in[3];
    const float* sa_b = (const float*)d_in[4];
    const float* ca_w = (const float*)d_in[5];
    const float* ca_b = (const float*)d_in[6];
    const float* ln_g = (const float*)d_in[7];
    const float* ln_b = (const float*)d_in[8];
    const float* w1   = (const float*)d_in[9];
    const float* b1   = (const float*)d_in[10];
    const float* w2   = (const float*)d_in[11];
    const float* b2   = (const float*)d_in[12];
    float* out = (float*)d_out;

    float *x, *t;
    __half *x16, *e16, *qkv16, *q16, *kv16, *vt16, *ao16, *ff16, *bias16;
    __half *wsa, *wca, *w1t, *w2t;
    cudaGetSymbolAddress((void**)&x,  g_x);
    cudaGetSymbolAddress((void**)&t,  g_t);
    cudaGetSymbolAddress((void**)&x16, g_x16);
    cudaGetSymbolAddress((void**)&e16, g_e16);
    cudaGetSymbolAddress((void**)&qkv16, g_qkv16);
    cudaGetSymbolAddress((void**)&q16, g_q16);
    cudaGetSymbolAddress((void**)&kv16, g_kv16);
    cudaGetSymbolAddress((void**)&vt16, g_vt16);
    cudaGetSymbolAddress((void**)&ao16, g_ao16);
    cudaGetSymbolAddress((void**)&ff16, g_ff16);
    cudaGetSymbolAddress((void**)&bias16, g_bias16);
    cudaGetSymbolAddress((void**)&wsa, g_wsa);
    cudaGetSymbolAddress((void**)&wca, g_wca);
    cudaGetSymbolAddress((void**)&w1t, g_w1t);
    cudaGetSymbolAddress((void**)&w2t, g_w2t);

    cudaFuncSetAttribute(gemm_mma_kernel<false,false>, cudaFuncAttributeMaxDynamicSharedMemorySize, GEMM_SMEM);
    cudaFuncSetAttribute(gemm_mma_kernel<false,true>,  cudaFuncAttributeMaxDynamicSharedMemorySize, GEMM_SMEM);
    cudaFuncSetAttribute(gemm_mma_kernel<true,true>,   cudaFuncAttributeMaxDynamicSharedMemorySize, GEMM_SMEM);
    cudaFuncSetAttribute(flash_kernel, cudaFuncAttributeMaxDynamicSharedMemorySize, FL_SMEM);

    const int nElem = Mrows * Dc;
    copy4_kernel<<<(nElem / 4 + 255) / 256, 256>>>((float4*)x, (const float4*)trg, nElem / 4);
    f2h_kernel<<<(nElem / 4 + 255) / 256, 256>>>(trg, x16, nElem);
    f2h_kernel<<<(nElem / 4 + 255) / 256, 256>>>(enc, e16, nElem);
    const int nMask = Bc * Nc * Nc;
    maskbias_kernel<<<(nMask / 4 + 255) / 256, 256>>>(mask, bias16, nMask);

    // upfront weight transposes (batched)
    wt_kernel<<<dim3(32, 32, 24), 256>>>(sa_w, wsa, Dc, Dc);
    wt_kernel<<<dim3(32, 32, 24), 256>>>(ca_w, wca, Dc, Dc);
    wt_kernel<<<dim3(128, 32, 6), 256>>>(w1, w1t, Dc, FFc);
    wt_kernel<<<dim3(32, 128, 6), 256>>>(w2, w2t, FFc, Dc);

    dim3 gQKV(3 * Dc / 128, Mrows / 128);    // (24, 32)
    dim3 gKV(2 * Dc / 128, Mrows / 128);     // (16, 32)
    dim3 gProj(Dc / 128, Mrows / 128);       // (8, 32)
    dim3 gFF1(FFc / 128, Mrows / 128);       // (32, 32)
    dim3 gFlash(Nc / 128, Bc * Hc);          // (4, 128)
    dim3 gVT(16, Bc * Hc);

    for (int l = 0; l < Lc; l++) {
        const __half* Ws = wsa + (size_t)l * 4 * Dc * Dc;
        const __half* Wc = wca + (size_t)l * 4 * Dc * Dc;
        const float* Bs = sa_b + (size_t)l * 4 * Dc;
        const float* Bcp = ca_b + (size_t)l * 4 * Dc;

        // ===== self-attention =====
        gemm_mma_kernel<false,true><<<gQKV, 256, GEMM_SMEM>>>(x16, Ws, Bs, qkv16, Mrows, 3 * Dc, Dc);
        vt_kernel<<<gVT, 256>>>(qkv16 + 2 * Dc, 3 * Dc, vt16);
        flash_kernel<<<gFlash, 256, FL_SMEM>>>(qkv16, 3 * Dc, qkv16 + Dc, 3 * Dc, vt16, bias16, ao16);
        gemm_mma_kernel<false,false><<<gProj, 256, GEMM_SMEM>>>(ao16, Ws + 3 * Dc * Dc, Bs + 3 * Dc, t, Mrows, Dc, Dc);
        add_ln_kernel<<<Mrows, 256>>>(t, x, ln_g + ((size_t)l * 3 + 0) * Dc, ln_b + ((size_t)l * 3 + 0) * Dc, x, x16);

        // ===== cross-attention =====
        gemm_mma_kernel<false,true><<<gProj, 256, GEMM_SMEM>>>(x16, Wc, Bcp, q16, Mrows, Dc, Dc);
        gemm_mma_kernel<false,true><<<gKV, 256, GEMM_SMEM>>>(e16, Wc + Dc * Dc, Bcp + Dc, kv16, Mrows, 2 * Dc, Dc);
        vt_kernel<<<gVT, 256>>>(kv16 + Dc, 2 * Dc, vt16);
        flash_kernel<<<gFlash, 256, FL_SMEM>>>(q16, Dc, kv16, 2 * Dc, vt16, nullptr, ao16);
        gemm_mma_kernel<false,false><<<gProj, 256, GEMM_SMEM>>>(ao16, Wc + 3 * Dc * Dc, Bcp + 3 * Dc, t, Mrows, Dc, Dc);
        add_ln_kernel<<<Mrows, 256>>>(t, x, ln_g + ((size_t)l * 3 + 1) * Dc, ln_b + ((size_t)l * 3 + 1) * Dc, x, x16);

        // ===== FFN =====
        gemm_mma_kernel<true,true><<<gFF1, 256, GEMM_SMEM>>>(x16, w1t + (size_t)l * Dc * FFc, b1 + (size_t)l * FFc, ff16, Mrows, FFc, Dc);
        gemm_mma_kernel<false,false><<<gProj, 256, GEMM_SMEM>>>(ff16, w2t + (size_t)l * FFc * Dc, b2 + (size_t)l * Dc, t, Mrows, Dc, FFc);
        add_ln_kernel<<<Mrows, 256>>>(t, x, ln_g + ((size_t)l * 3 + 2) * Dc, ln_b + ((size_t)l * 3 + 2) * Dc, x, x16);
    }

    copy4_kernel<<<(nElem / 4 + 255) / 256, 256>>>((float4*)out, (const float4*)x, nElem / 4);
}

// round 7
// speedup vs baseline: 7.1000x; 1.0814x over previous
#include <cuda_runtime.h>
#include <cuda_fp16.h>
#include <math.h>
#include <stdint.h>

// Problem constants
#define Lc   6
#define Dc   1024
#define Hc   16
#define DHc  64
#define FFc  4096
#define Bc   8
#define Nc   512
#define Mrows (Bc*Nc)          // 4096
#define EPSc 1e-12f

// ------------------------------------------------------------------
// Scratch (device globals)
// ------------------------------------------------------------------
__device__ float g_x [Mrows*Dc];
__device__ float g_t [Mrows*Dc];

__device__ __half g_x16[Mrows*Dc];
__device__ __half g_e16[Mrows*Dc];
__device__ __half g_qkv16[(size_t)Mrows*3*Dc];  // fused QKV (self) [4096][3072]
__device__ __half g_q16[Mrows*Dc];              // cross Q
__device__ __half g_kv16[(size_t)Mrows*2*Dc];   // cross KV [4096][2048]
__device__ __half g_vt16[Mrows*Dc];             // [bh][dh=64][kv=512]
__device__ __half g_ao16[Mrows*Dc];
__device__ __half g_ff16[(size_t)Mrows*FFc];
__device__ __half g_bias16[(size_t)Bc*Nc*Nc];   // mask additive bias fp16

// transposed fp16 weights (built once per launch)
__device__ __half g_wsa[(size_t)Lc*4*Dc*Dc];
__device__ __half g_wca[(size_t)Lc*4*Dc*Dc];
__device__ __half g_w1t[(size_t)Lc*Dc*FFc];
__device__ __half g_w2t[(size_t)Lc*FFc*Dc];

// ------------------------------------------------------------------
// PTX helpers
// ------------------------------------------------------------------
__device__ __forceinline__ uint32_t smem_u32(const void* p) {
    uint32_t a;
    asm("{ .reg .u64 t; cvta.to.shared.u64 t, %1; cvt.u32.u64 %0, t; }" : "=r"(a) : "l"(p));
    return a;
}
__device__ __forceinline__ void cp16(uint32_t dst, const void* src) {
    asm volatile("cp.async.cg.shared.global [%0], [%1], 16;" :: "r"(dst), "l"(src) : "memory");
}
#define CP_COMMIT() asm volatile("cp.async.commit_group;" ::: "memory")

__device__ __forceinline__ void ldsm4(uint32_t& r0, uint32_t& r1, uint32_t& r2, uint32_t& r3, uint32_t addr) {
    asm volatile("ldmatrix.sync.aligned.m8n8.x4.shared.b16 {%0,%1,%2,%3}, [%4];"
        : "=r"(r0), "=r"(r1), "=r"(r2), "=r"(r3) : "r"(addr));
}
__device__ __forceinline__ void mma16816(float* c, const uint32_t* a, uint32_t b0, uint32_t b1) {
    asm volatile(
        "mma.sync.aligned.m16n8k16.row.col.f32.f16.f16.f32 "
        "{%0,%1,%2,%3}, {%4,%5,%6,%7}, {%8,%9}, {%0,%1,%2,%3};"
        : "+f"(c[0]), "+f"(c[1]), "+f"(c[2]), "+f"(c[3])
        : "r"(a[0]), "r"(a[1]), "r"(a[2]), "r"(a[3]), "r"(b0), "r"(b1));
}
__device__ __forceinline__ uint32_t packh2(float a, float b) {
    __half2 h = __floats2half2_rn(a, b);
    return *(uint32_t*)&h;
}

// ==================================================================
// Dense GEMM: C[M,N] = A[M,K] @ Bt[N,K]^T + bias (+ReLU). fp16/fp32 out.
// BM=128, BN=128, BK=64, 3-stage cp.async, 256 threads (8 warps 4x2).
// Stage: A 128 x 144B + B 128 x 144B = 36864 B. 3 stages = 110592 B.
// Requires K % 64 == 0 (all call sites: K = 1024 or 4096).
// ==================================================================
#define GEMM_STAGE 36864
#define GEMM_SMEM  (3 * GEMM_STAGE)

__device__ __forceinline__ void cp_stage_g(uint32_t sbase,
    const __half* __restrict__ A, const __half* __restrict__ B,
    int m0, int n0, int k0, int K, int tid)
{
#pragma unroll
    for (int j = 0; j < 4; j++) {
        int idx = tid + 256 * j;         // 0..1023
        int row = idx >> 3;              // 0..127
        int c = idx & 7;                 // 0..7 (16B chunks over 128B row)
        uint32_t d = (uint32_t)(row * 144 + c * 16);
        cp16(sbase + d,         A + (size_t)(m0 + row) * K + k0 + c * 8);
        cp16(sbase + 18432 + d, B + (size_t)(n0 + row) * K + k0 + c * 8);
    }
}

template<bool RELU, bool HOUT>
__global__ void __launch_bounds__(256, 2)
gemm_mma_kernel(const __half* __restrict__ A, const __half* __restrict__ B,
                const float* __restrict__ bias, void* __restrict__ Cout,
                int M, int N, int K)
{
    extern __shared__ char sm_[];
    const uint32_t sb = smem_u32(sm_);
    const int tid = threadIdx.x;
    const int wid = tid >> 5;
    const int l = tid & 31;
    const int m0 = blockIdx.y * 128;
    const int n0 = blockIdx.x * 128;
    const int wm = (wid >> 1) * 32;
    const int wn = (wid & 1) * 64;
    const int KT = K >> 6;               // K / 64

    float c[2][8][4];
#pragma unroll
    for (int i = 0; i < 2; i++)
#pragma unroll
        for (int j = 0; j < 8; j++)
#pragma unroll
            for (int r = 0; r < 4; r++) c[i][j][r] = 0.f;

    // prologue: stages 0,1
#pragma unroll
    for (int s = 0; s < 2; s++) {
        cp_stage_g(sb + s * GEMM_STAGE, A, B, m0, n0, s * 64, K, tid);
        CP_COMMIT();
    }

    const uint32_t aoff = (uint32_t)((wm + (l & 15)) * 144 + (l >> 4) * 16);
    const uint32_t boff = (uint32_t)((wn + (l & 7) + ((l >> 3) & 1) * 8) * 144 + (l >> 4) * 16);

    int stage = 0;
    for (int kt = 0; kt < KT; kt++) {
        asm volatile("cp.async.wait_group 1;" ::: "memory");
        __syncthreads();

        const int pf = kt + 2;
        int pstage = stage + 2; if (pstage >= 3) pstage -= 3;
        if (pf < KT) cp_stage_g(sb + pstage * GEMM_STAGE, A, B, m0, n0, pf * 64, K, tid);
        CP_COMMIT();

        const uint32_t sA = sb + stage * GEMM_STAGE;
        const uint32_t sB = sA + 18432;

#pragma unroll
        for (int kk = 0; kk < 4; kk++) {
            uint32_t a[2][4], b[4][4];
            ldsm4(a[0][0], a[0][1], a[0][2], a[0][3], sA + aoff + kk * 32);
            ldsm4(a[1][0], a[1][1], a[1][2], a[1][3], sA + aoff + 16 * 144 + kk * 32);
#pragma unroll
            for (int j = 0; j < 4; j++)
                ldsm4(b[j][0], b[j][1], b[j][2], b[j][3], sB + boff + j * 16 * 144 + kk * 32);
#pragma unroll
            for (int mi = 0; mi < 2; mi++)
#pragma unroll
                for (int nj = 0; nj < 8; nj++)
                    mma16816(c[mi][nj], a[mi], b[nj >> 1][nj & 1], b[nj >> 1][(nj & 1) + 2]);
        }
        if (++stage == 3) stage = 0;
    }

    const int row0 = m0 + wm + (l >> 2);
    const int colb = n0 + wn + (l & 3) * 2;
#pragma unroll
    for (int mi = 0; mi < 2; mi++) {
#pragma unroll
        for (int nj = 0; nj < 8; nj++) {
            const int col = colb + nj * 8;
            const float b0 = bias[col], b1 = bias[col + 1];
            float v0 = c[mi][nj][0] + b0;
            float v1 = c[mi][nj][1] + b1;
            float v2 = c[mi][nj][2] + b0;
            float v3 = c[mi][nj][3] + b1;
            if (RELU) {
                v0 = fmaxf(v0, 0.f); v1 = fmaxf(v1, 0.f);
                v2 = fmaxf(v2, 0.f); v3 = fmaxf(v3, 0.f);
            }
            const int r0 = row0 + mi * 16;
            if (HOUT) {
                __half* C = (__half*)Cout;
                *(__half2*)&C[(size_t)r0 * N + col]       = __floats2half2_rn(v0, v1);
                *(__half2*)&C[(size_t)(r0 + 8) * N + col] = __floats2half2_rn(v2, v3);
            } else {
                float* C = (float*)Cout;
                float2 p0; p0.x = v0; p0.y = v1;
                float2 p1; p1.x = v2; p1.y = v3;
                *(float2*)&C[(size_t)r0 * N + col] = p0;
                *(float2*)&C[(size_t)(r0 + 8) * N + col] = p1;
            }
        }
    }
}

// ==================================================================
// Flash attention: O = softmax(Q K^T / 8 + bias) V
// ==================================================================
#define FL_SMEM (18432 + 2 * 18432)

__global__ void __launch_bounds__(256, 2)
flash_kernel(const __half* __restrict__ Qg, int qStride,
             const __half* __restrict__ Kg, int kStride,
             const __half* __restrict__ VTg,
             const __half* __restrict__ biasMask,
             __half* __restrict__ O)
{
    extern __shared__ char sm_[];
    const uint32_t sb = smem_u32(sm_);
    const int tid = threadIdx.x;
    const int wid = tid >> 5;
    const int l = tid & 31;
    const int bh = blockIdx.y;
    const int b = bh >> 4;
    const int h = bh & 15;
    const int q0 = blockIdx.x * 128;
    const int wm = wid * 16;

    const __half* Qb = Qg + h * DHc;
    const __half* Kb = Kg + h * DHc;
    const __half* VTb = VTg + (size_t)bh * DHc * Nc;

    const uint32_t sQ = sb;

#pragma unroll
    for (int j = 0; j < 4; j++) {
        int idx = tid + 256 * j;
        int row = idx >> 3;
        int c = idx & 7;
        cp16(sQ + (uint32_t)(row * 144 + c * 16),
             Qb + (size_t)(b * Nc + q0 + row) * qStride + c * 8);
    }
    {
        uint32_t sK = sb + 18432;
        uint32_t sV = sK + 9216;
#pragma unroll
        for (int j = 0; j < 2; j++) {
            int idx = tid + 256 * j;
            int row = idx >> 3;
            int c = idx & 7;
            cp16(sK + (uint32_t)(row * 144 + c * 16),
                 Kb + (size_t)(b * Nc + row) * kStride + c * 8);
            cp16(sV + (uint32_t)(row * 144 + c * 16),
                 VTb + (size_t)row * Nc + c * 8);
        }
    }
    CP_COMMIT();

    float o[8][4];
#pragma unroll
    for (int j = 0; j < 8; j++)
#pragma unroll
        for (int r = 0; r < 4; r++) o[j][r] = 0.f;
    float mrow[2] = { -INFINITY, -INFINITY };
    float lsum[2] = { 0.f, 0.f };

    const uint32_t aoff = (uint32_t)((wm + (l & 15)) * 144 + (l >> 4) * 16);
    const uint32_t boff = (uint32_t)(((l & 7) + ((l >> 3) & 1) * 8) * 144 + (l >> 4) * 16);
    const int r0g = q0 + wm + (l >> 2);

    for (int t = 0; t < 8; t++) {
        if (t < 7) {
            uint32_t sK = sb + 18432 + ((t + 1) & 1) * 18432;
            uint32_t sV = sK + 9216;
            const int kv0 = (t + 1) * 64;
#pragma unroll
            for (int j = 0; j < 2; j++) {
                int idx = tid + 256 * j;
                int row = idx >> 3;
                int c = idx & 7;
                cp16(sK + (uint32_t)(row * 144 + c * 16),
                     Kb + (size_t)(b * Nc + kv0 + row) * kStride + c * 8);
                cp16(sV + (uint32_t)(row * 144 + c * 16),
                     VTb + (size_t)row * Nc + kv0 + c * 8);
            }
            CP_COMMIT();
            asm volatile("cp.async.wait_group 1;" ::: "memory");
        } else {
            asm volatile("cp.async.wait_group 0;" ::: "memory");
        }
        __syncthreads();

        const uint32_t sK = sb + 18432 + (t & 1) * 18432;
        const uint32_t sV = sK + 9216;

        float s[8][4];
#pragma unroll
        for (int j = 0; j < 8; j++)
#pragma unroll
            for (int r = 0; r < 4; r++) s[j][r] = 0.f;

#pragma unroll
        for (int kk = 0; kk < 4; kk++) {
            uint32_t a[4], bf[4][4];
            ldsm4(a[0], a[1], a[2], a[3], sQ + aoff + kk * 32);
#pragma unroll
            for (int j = 0; j < 4; j++)
                ldsm4(bf[j][0], bf[j][1], bf[j][2], bf[j][3], sK + boff + j * 16 * 144 + kk * 32);
#pragma unroll
            for (int j = 0; j < 4; j++) {
                mma16816(s[2 * j],     a, bf[j][0], bf[j][2]);
                mma16816(s[2 * j + 1], a, bf[j][1], bf[j][3]);
            }
        }

        const int colb = t * 64 + (l & 3) * 2;
        if (biasMask != nullptr) {
#pragma unroll
            for (int nj = 0; nj < 8; nj++) {
                const int col = colb + nj * 8;
                __half2 b0 = *(const __half2*)&biasMask[((size_t)b * Nc + r0g) * Nc + col];
                __half2 b1 = *(const __half2*)&biasMask[((size_t)b * Nc + r0g + 8) * Nc + col];
                s[nj][0] = s[nj][0] * 0.125f + __low2float(b0);
                s[nj][1] = s[nj][1] * 0.125f + __high2float(b0);
                s[nj][2] = s[nj][2] * 0.125f + __low2float(b1);
                s[nj][3] = s[nj][3] * 0.125f + __high2float(b1);
            }
        } else {
#pragma unroll
            for (int nj = 0; nj < 8; nj++) {
                s[nj][0] *= 0.125f; s[nj][1] *= 0.125f;
                s[nj][2] *= 0.125f; s[nj][3] *= 0.125f;
            }
        }

        float m0 = -INFINITY, m1 = -INFINITY;
#pragma unroll
        for (int nj = 0; nj < 8; nj++) {
            m0 = fmaxf(m0, fmaxf(s[nj][0], s[nj][1]));
            m1 = fmaxf(m1, fmaxf(s[nj][2], s[nj][3]));
        }
        m0 = fmaxf(m0, __shfl_xor_sync(0xffffffffu, m0, 1));
        m0 = fmaxf(m0, __shfl_xor_sync(0xffffffffu, m0, 2));
        m1 = fmaxf(m1, __shfl_xor_sync(0xffffffffu, m1, 1));
        m1 = fmaxf(m1, __shfl_xor_sync(0xffffffffu, m1, 2));

        const float mn0 = fmaxf(mrow[0], m0);
        const float mn1 = fmaxf(mrow[1], m1);
        const float sc0 = expf(mrow[0] - mn0);
        const float sc1 = expf(mrow[1] - mn1);
        mrow[0] = mn0; mrow[1] = mn1;

        float rs0 = 0.f, rs1 = 0.f;
#pragma unroll
        for (int nj = 0; nj < 8; nj++) {
            s[nj][0] = expf(s[nj][0] - mn0);
            s[nj][1] = expf(s[nj][1] - mn0);
            s[nj][2] = expf(s[nj][2] - mn1);
            s[nj][3] = expf(s[nj][3] - mn1);
            rs0 += s[nj][0] + s[nj][1];
            rs1 += s[nj][2] + s[nj][3];
        }
        rs0 += __shfl_xor_sync(0xffffffffu, rs0, 1);
        rs0 += __shfl_xor_sync(0xffffffffu, rs0, 2);
        rs1 += __shfl_xor_sync(0xffffffffu, rs1, 1);
        rs1 += __shfl_xor_sync(0xffffffffu, rs1, 2);
        lsum[0] = lsum[0] * sc0 + rs0;
        lsum[1] = lsum[1] * sc1 + rs1;

#pragma unroll
        for (int j = 0; j < 8; j++) {
            o[j][0] *= sc0; o[j][1] *= sc0;
            o[j][2] *= sc1; o[j][3] *= sc1;
        }

#pragma unroll
        for (int kk = 0; kk < 4; kk++) {
            uint32_t a[4];
            a[0] = packh2(s[2 * kk][0],     s[2 * kk][1]);
            a[1] = packh2(s[2 * kk][2],     s[2 * kk][3]);
            a[2] = packh2(s[2 * kk + 1][0], s[2 * kk + 1][1]);
            a[3] = packh2(s[2 * kk + 1][2], s[2 * kk + 1][3]);
            uint32_t bf[4][4];
#pragma unroll
            for (int j = 0; j < 4; j++)
                ldsm4(bf[j][0], bf[j][1], bf[j][2], bf[j][3], sV + boff + j * 16 * 144 + kk * 32);
#pragma unroll
            for (int j = 0; j < 4; j++) {
                mma16816(o[2 * j],     a, bf[j][0], bf[j][2]);
                mma16816(o[2 * j + 1], a, bf[j][1], bf[j][3]);
            }
        }
        __syncthreads();
    }

    const float inv0 = 1.f / lsum[0];
    const float inv1 = 1.f / lsum[1];
#pragma unroll
    for (int njo = 0; njo < 8; njo++) {
        const int gc = h * DHc + njo * 8 + (l & 3) * 2;
        *(__half2*)&O[(size_t)(b * Nc + r0g) * Dc + gc] =
            __floats2half2_rn(o[njo][0] * inv0, o[njo][1] * inv0);
        *(__half2*)&O[(size_t)(b * Nc + r0g + 8) * Dc + gc] =
            __floats2half2_rn(o[njo][2] * inv1, o[njo][3] * inv1);
    }
}

// ==================================================================
// V transpose: V (head-strided rows) -> vt16[bh][dh][kv]
// ==================================================================
__global__ void __launch_bounds__(256)
vt_kernel(const __half* __restrict__ V, int vStride, __half* __restrict__ VT)
{
    __shared__ __half sm[32][65];
    const int bh = blockIdx.y;
    const int b = bh >> 4;
    const int h = bh & 15;
    const int kv0 = blockIdx.x * 32;
    const int tid = threadIdx.x;

#pragma unroll
    for (int i = 0; i < 4; i++) {
        int idx = tid + i * 256;
        int kv = idx >> 5;
        int dp = idx & 31;
        __half2 v = *(const __half2*)&V[(size_t)(b * Nc + kv0 + kv) * vStride + h * DHc + dp * 2];
        sm[kv][dp * 2]     = __low2half(v);
        sm[kv][dp * 2 + 1] = __high2half(v);
    }
    __syncthreads();
#pragma unroll
    for (int i = 0; i < 4; i++) {
        int idx = tid + i * 256;
        int dh = idx >> 4;
        int kp = idx & 15;
        __half2 o = __halves2half2(sm[kp * 2][dh], sm[kp * 2 + 1][dh]);
        *(__half2*)&VT[(size_t)bh * DHc * Nc + (size_t)dh * Nc + kv0 + kp * 2] = o;
    }
}

// ==================================================================
// Mask -> fp16 additive bias (0 / -10000)
// ==================================================================
__global__ void __launch_bounds__(256)
maskbias_kernel(const int* __restrict__ mask, __half* __restrict__ bias, int n)
{
    int i = (blockIdx.x * 256 + threadIdx.x) * 4;
    if (i >= n) return;
    int4 m = *(const int4*)(mask + i);
    __half z = __float2half(0.f), neg = __float2half(-10000.f);
    bias[i]     = m.x ? z : neg;
    bias[i + 1] = m.y ? z : neg;
    bias[i + 2] = m.z ? z : neg;
    bias[i + 3] = m.w ? z : neg;
}

// ==================================================================
// Residual + LayerNorm -> fp32 x AND fp16 x16
// ==================================================================
__global__ void __launch_bounds__(256)
add_ln_kernel(const float* __restrict__ A, const float* __restrict__ X,
              const float* __restrict__ gamma, const float* __restrict__ beta,
              float* __restrict__ out, __half* __restrict__ out16)
{
    const size_t row = blockIdx.x;
    const int tid = threadIdx.x;
    float vals[4];
    float s = 0.f, ss = 0.f;
#pragma unroll
    for (int i = 0; i < 4; i++) {
        int c = tid + i * 256;
        float v = A[row * Dc + c] + X[row * Dc + c];
        vals[i] = v;
        s += v;
        ss += v * v;
    }
    __shared__ float sa[8], sb_[8];
    int lane = tid & 31, w = tid >> 5;
    for (int o = 16; o > 0; o >>= 1) {
        s  += __shfl_down_sync(0xffffffffu, s, o);
        ss += __shfl_down_sync(0xffffffffu, ss, o);
    }
    if (lane == 0) { sa[w] = s; sb_[w] = ss; }
    __syncthreads();
    if (w == 0) {
        s  = (lane < 8) ? sa[lane] : 0.f;
        ss = (lane < 8) ? sb_[lane] : 0.f;
        for (int o = 4; o > 0; o >>= 1) {
            s  += __shfl_down_sync(0xffffffffu, s, o);
            ss += __shfl_down_sync(0xffffffffu, ss, o);
        }
        if (lane == 0) { sa[0] = s; sb_[0] = ss; }
    }
    __syncthreads();
    float mean = sa[0] * (1.f / Dc);
    float var = sb_[0] * (1.f / Dc) - mean * mean;
    float inv = rsqrtf(var + EPSc);
#pragma unroll
    for (int i = 0; i < 4; i++) {
        int c = tid + i * 256;
        float o = gamma[c] * (vals[i] - mean) * inv + beta[c];
        out[row * Dc + c] = o;
        out16[row * Dc + c] = __float2half(o);
    }
}

// ==================================================================
// Batched weight transpose+convert: W[z][K,N] fp32 -> T[z][N,K] fp16
// ==================================================================
__global__ void __launch_bounds__(256)
wt_kernel(const float* __restrict__ Wbase, __half* __restrict__ Tbase, int K, int N)
{
    __shared__ float t[32][33];
    const float* W = Wbase + (size_t)blockIdx.z * K * N;
    __half* T = Tbase + (size_t)blockIdx.z * K * N;
    const int n0 = blockIdx.x * 32;
    const int k0 = blockIdx.y * 32;
    const int tx = threadIdx.x & 31;
    const int ty = threadIdx.x >> 5;
#pragma unroll
    for (int i = 0; i < 4; i++)
        t[ty + i * 8][tx] = W[(size_t)(k0 + ty + i * 8) * N + n0 + tx];
    __syncthreads();
#pragma unroll
    for (int i = 0; i < 4; i++)
        T[(size_t)(n0 + ty + i * 8) * K + k0 + tx] = __float2half(t[tx][ty + i * 8]);
}

// ------------------------------------------------------------------
// misc
// ------------------------------------------------------------------
__global__ void copy4_kernel(float4* __restrict__ dst, const float4* __restrict__ src, int n4) {
    int i = blockIdx.x * blockDim.x + threadIdx.x;
    if (i < n4) dst[i] = src[i];
}
__global__ void __launch_bounds__(256)
f2h_kernel(const float* __restrict__ in, __half* __restrict__ out, int n)
{
    int i = (blockIdx.x * 256 + threadIdx.x) * 4;
    if (i >= n) return;
    float4 v = *(const float4*)(in + i);
    *(__half2*)(out + i)     = __floats2half2_rn(v.x, v.y);
    *(__half2*)(out + i + 2) = __floats2half2_rn(v.z, v.w);
}

// ------------------------------------------------------------------
// Host orchestration
// ------------------------------------------------------------------
extern "C" void kernel_launch(void* const* d_in, const int* in_sizes, int n_in,
                              void* d_out, int out_size)
{
    const float* trg  = (const float*)d_in[0];
    const float* enc  = (const float*)d_in[1];
    const int*   mask = (const int*)  d_in[2];
    const float* sa_w = (const float*)d_in[3];
    const float* sa_b = (const float*)d_in[4];
    const float* ca_w = (const float*)d_in[5];
    const float* ca_b = (const float*)d_in[6];
    const float* ln_g = (const float*)d_in[7];
    const float* ln_b = (const float*)d_in[8];
    const float* w1   = (const float*)d_in[9];
    const float* b1   = (const float*)d_in[10];
    const float* w2   = (const float*)d_in[11];
    const float* b2   = (const float*)d_in[12];
    float* out = (float*)d_out;

    float *x, *t;
    __half *x16, *e16, *qkv16, *q16, *kv16, *vt16, *ao16, *ff16, *bias16;
    __half *wsa, *wca, *w1t, *w2t;
    cudaGetSymbolAddress((void**)&x,  g_x);
    cudaGetSymbolAddress((void**)&t,  g_t);
    cudaGetSymbolAddress((void**)&x16, g_x16);
    cudaGetSymbolAddress((void**)&e16, g_e16);
    cudaGetSymbolAddress((void**)&qkv16, g_qkv16);
    cudaGetSymbolAddress((void**)&q16, g_q16);
    cudaGetSymbolAddress((void**)&kv16, g_kv16);
    cudaGetSymbolAddress((void**)&vt16, g_vt16);
    cudaGetSymbolAddress((void**)&ao16, g_ao16);
    cudaGetSymbolAddress((void**)&ff16, g_ff16);
    cudaGetSymbolAddress((void**)&bias16, g_bias16);
    cudaGetSymbolAddress((void**)&wsa, g_wsa);
    cudaGetSymbolAddress((void**)&wca, g_wca);
    cudaGetSymbolAddress((void**)&w1t, g_w1t);
    cudaGetSymbolAddress((void**)&w2t, g_w2t);

    cudaFuncSetAttribute(gemm_mma_kernel<false,false>, cudaFuncAttributeMaxDynamicSharedMemorySize, GEMM_SMEM);
    cudaFuncSetAttribute(gemm_mma_kernel<false,true>,  cudaFuncAttributeMaxDynamicSharedMemorySize, GEMM_SMEM);
    cudaFuncSetAttribute(gemm_mma_kernel<true,true>,   cudaFuncAttributeMaxDynamicSharedMemorySize, GEMM_SMEM);
    cudaFuncSetAttribute(flash_kernel, cudaFuncAttributeMaxDynamicSharedMemorySize, FL_SMEM);

    const int nElem = Mrows * Dc;
    copy4_kernel<<<(nElem / 4 + 255) / 256, 256>>>((float4*)x, (const float4*)trg, nElem / 4);
    f2h_kernel<<<(nElem / 4 + 255) / 256, 256>>>(trg, x16, nElem);
    f2h_kernel<<<(nElem / 4 + 255) / 256, 256>>>(enc, e16, nElem);
    const int nMask = Bc * Nc * Nc;
    maskbias_kernel<<<(nMask / 4 + 255) / 256, 256>>>(mask, bias16, nMask);

    // upfront weight transposes (batched)
    wt_kernel<<<dim3(32, 32, 24), 256>>>(sa_w, wsa, Dc, Dc);
    wt_kernel<<<dim3(32, 32, 24), 256>>>(ca_w, wca, Dc, Dc);
    wt_kernel<<<dim3(128, 32, 6), 256>>>(w1, w1t, Dc, FFc);
    wt_kernel<<<dim3(32, 128, 6), 256>>>(w2, w2t, FFc, Dc);

    dim3 gQKV(3 * Dc / 128, Mrows / 128);    // (24, 32)
    dim3 gKV(2 * Dc / 128, Mrows / 128);     // (16, 32)
    dim3 gProj(Dc / 128, Mrows / 128);       // (8, 32)
    dim3 gFF1(FFc / 128, Mrows / 128);       // (32, 32)
    dim3 gFlash(Nc / 128, Bc * Hc);          // (4, 128)
    dim3 gVT(16, Bc * Hc);

    for (int l = 0; l < Lc; l++) {
        const __half* Ws = wsa + (size_t)l * 4 * Dc * Dc;
        const __half* Wc = wca + (size_t)l * 4 * Dc * Dc;
        const float* Bs = sa_b + (size_t)l * 4 * Dc;
        const float* Bcp = ca_b + (size_t)l * 4 * Dc;

        // ===== self-attention =====
        gemm_mma_kernel<false,true><<<gQKV, 256, GEMM_SMEM>>>(x16, Ws, Bs, qkv16, Mrows, 3 * Dc, Dc);
        vt_kernel<<<gVT, 256>>>(qkv16 + 2 * Dc, 3 * Dc, vt16);
        flash_kernel<<<gFlash, 256, FL_SMEM>>>(qkv16, 3 * Dc, qkv16 + Dc, 3 * Dc, vt16, bias16, ao16);
        gemm_mma_kernel<false,false><<<gProj, 256, GEMM_SMEM>>>(ao16, Ws + 3 * Dc * Dc, Bs + 3 * Dc, t, Mrows, Dc, Dc);
        add_ln_kernel<<<Mrows, 256>>>(t, x, ln_g + ((size_t)l * 3 + 0) * Dc, ln_b + ((size_t)l * 3 + 0) * Dc, x, x16);

        // ===== cross-attention =====
        gemm_mma_kernel<false,true><<<gProj, 256, GEMM_SMEM>>>(x16, Wc, Bcp, q16, Mrows, Dc, Dc);
        gemm_mma_kernel<false,true><<<gKV, 256, GEMM_SMEM>>>(e16, Wc + Dc * Dc, Bcp + Dc, kv16, Mrows, 2 * Dc, Dc);
        vt_kernel<<<gVT, 256>>>(kv16 + Dc, 2 * Dc, vt16);
        flash_kernel<<<gFlash, 256, FL_SMEM>>>(q16, Dc, kv16, 2 * Dc, vt16, nullptr, ao16);
        gemm_mma_kernel<false,false><<<gProj, 256, GEMM_SMEM>>>(ao16, Wc + 3 * Dc * Dc, Bcp + 3 * Dc, t, Mrows, Dc, Dc);
        add_ln_kernel<<<Mrows, 256>>>(t, x, ln_g + ((size_t)l * 3 + 1) * Dc, ln_b + ((size_t)l * 3 + 1) * Dc, x, x16);

        // ===== FFN =====
        gemm_mma_kernel<true,true><<<gFF1, 256, GEMM_SMEM>>>(x16, w1t + (size_t)l * Dc * FFc, b1 + (size_t)l * FFc, ff16, Mrows, FFc, Dc);
        gemm_mma_kernel<false,false><<<gProj, 256, GEMM_SMEM>>>(ff16, w2t + (size_t)l * FFc * Dc, b2 + (size_t)l * Dc, t, Mrows, Dc, FFc);
        add_ln_kernel<<<Mrows, 256>>>(t, x, ln_g + ((size_t)l * 3 + 2) * Dc, ln_b + ((size_t)l * 3 + 2) * Dc, x, x16);
    }

    copy4_kernel<<<(nElem / 4 + 255) / 256, 256>>>((float4*)out, (const float4*)x, nElem / 4);
}